// round 1
// baseline (speedup 1.0000x reference)
#include <cuda_runtime.h>
#include <cstdint>

// Problem constants
#define B_   16
#define C_   256      // Cin == Cout == 256
#define S_   512      // style dim
#define HW_  64
#define KK_  9        // 3x3
#define PIX_ (HW_*HW_)        // 4096
#define STYLE_SCALE 0.03125f  // 2^-0.5 * 512^-0.5 = 1/32
#define EPS_ 1e-8f

// ---------------- scratch (device globals: allocation-free rule) -------------
__device__ float g_h[B_ * C_ * PIX_];        // intermediate activation (67MB)
__device__ float g_w1t[C_ * C_ * KK_];       // conv1 weights transposed [ci][k][co]
__device__ float g_w2t[C_ * C_ * KK_];
__device__ float g_style1[B_ * C_];
__device__ float g_style2[B_ * C_];
__device__ float g_demod1[B_ * C_];
__device__ float g_demod2[B_ * C_];

// ---------------- f32x2 helpers ---------------------------------------------
__device__ __forceinline__ void fma2(unsigned long long &d, unsigned long long a,
                                     unsigned long long b) {
    asm("fma.rn.f32x2 %0, %1, %2, %0;" : "+l"(d) : "l"(a), "l"(b));
}
__device__ __forceinline__ unsigned long long pack2(float lo, float hi) {
    unsigned long long r;
    asm("mov.b64 %0, {%1, %2};" : "=l"(r) : "f"(lo), "f"(hi));
    return r;
}
__device__ __forceinline__ void unpack2(unsigned long long v, float &lo, float &hi) {
    asm("mov.b64 {%0, %1}, %2;" : "=f"(lo), "=f"(hi) : "l"(v));
}

// ---------------- prep: transpose weights [co][ci][k] -> [ci*9+k][co] --------
__global__ void transpose_w_kernel(const float* __restrict__ w, float* __restrict__ wt) {
    int e = blockIdx.x * 256 + threadIdx.x;           // e = (ci*9+k)*256 + co
    if (e >= C_ * C_ * KK_) return;
    int co   = e & 255;
    int rest = e >> 8;                                // ci*9 + k
    int k    = rest % 9;
    int ci   = rest / 9;
    wt[e] = w[co * (C_ * KK_) + ci * KK_ + k];
}

// ---------------- prep: style = (w * scale) @ sw^T + sb ----------------------
// one warp per (b, c) output; lanes stride over style dim
__global__ void style_kernel(const float* __restrict__ wvec,   // [B, S]
                             const float* __restrict__ sw,     // [C, S]
                             const float* __restrict__ sb,     // [C]
                             float* __restrict__ style) {      // [B, C]
    int gw   = blockIdx.x * 8 + (threadIdx.x >> 5);  // global warp id
    int lane = threadIdx.x & 31;
    if (gw >= B_ * C_) return;
    int b = gw >> 8;          // /C_
    int c = gw & 255;
    const float* wv = wvec + b * S_;
    const float* sr = sw + c * S_;
    float sum = 0.f;
    #pragma unroll 4
    for (int s = lane; s < S_; s += 32) sum += wv[s] * sr[s];
    #pragma unroll
    for (int off = 16; off > 0; off >>= 1)
        sum += __shfl_down_sync(0xffffffffu, sum, off);
    if (lane == 0) style[b * C_ + c] = sum * STYLE_SCALE + sb[c];
}

// ---------------- prep: demod = rsqrt(sum_ci style^2 * sum_k w^2 + eps) ------
// one block per batch; thread = co; coalesced reads of transposed weights
__global__ void demod_kernel(const float* __restrict__ wt,     // [C*9, C]
                             const float* __restrict__ style,  // [B, C]
                             float* __restrict__ demod) {      // [B, C]
    __shared__ float st2[C_];
    int b  = blockIdx.x;
    int co = threadIdx.x;
    float s = style[b * C_ + co];
    st2[co] = s * s;
    __syncthreads();
    float acc = 0.f;
    int ci = 0, kc = 0;
    #pragma unroll 8
    for (int idx = 0; idx < C_ * KK_; idx++) {
        float v = wt[idx * C_ + co];
        acc += st2[ci] * v * v;
        if (++kc == 9) { kc = 0; ci++; }
    }
    demod[b * C_ + co] = rsqrtf(acc + EPS_);
}

// ---------------- main conv: modulated 3x3 conv + noise + leaky relu ---------
// grid: (16 spatial tiles, 4 co-tiles, 16 batches); block 256 threads
// thread: 16 cout x 4 pixels (column of 4 rows), f32x2-packed accumulators
#define CI_CHUNK 8
#define SW_IN 20   // padded row stride (conflict-free for 2 row-groups x 16 cols)

__global__ __launch_bounds__(256, 2)
void conv_mod_kernel(const float* __restrict__ x,      // [B, C, 64, 64]
                     const float* __restrict__ wt,     // [C*9, C] transposed
                     const float* __restrict__ style,  // [B, C]
                     const float* __restrict__ demod,  // [B, C]
                     const float* __restrict__ nw,     // [C]
                     const float* __restrict__ noise,  // [B, 1, 64, 64]
                     float* __restrict__ out) {        // [B, C, 64, 64]
    __shared__ float  s_in[CI_CHUNK][18][SW_IN];
    __shared__ float2 s_w[CI_CHUNK][KK_][64];

    const int tid    = threadIdx.x;
    const int b      = blockIdx.z;
    const int co0    = blockIdx.y << 6;                 // * 64
    const int tile_r = (blockIdx.x >> 2) << 4;          // * 16
    const int tile_c = (blockIdx.x & 3) << 4;

    const int co_sub = tid >> 6;                        // 0..3 (uniform per warp-pair)
    const int pg     = tid & 63;
    const int col    = pg & 15;                         // 0..15
    const int row4   = (pg >> 4) << 2;                  // 0,4,8,12

    unsigned long long acc[16][2];
    #pragma unroll
    for (int j = 0; j < 16; j++) { acc[j][0] = 0ULL; acc[j][1] = 0ULL; }

    const float* xb  = x + ((size_t)b << 20);           // b * C_*PIX_
    const float* stb = style + (b << 8);

    for (int ci0 = 0; ci0 < C_; ci0 += CI_CHUNK) {
        // ---- load style-modulated input tile (with halo, zero-padded) ----
        for (int e = tid; e < CI_CHUNK * 18 * 18; e += 256) {
            int ci  = e / 324;
            int rem = e - ci * 324;
            int r   = rem / 18;
            int c   = rem - r * 18;
            int gr  = tile_r + r - 1;
            int gc  = tile_c + c - 1;
            float v = 0.f;
            if ((unsigned)gr < 64u && (unsigned)gc < 64u)
                v = xb[((ci0 + ci) << 12) + (gr << 6) + gc] * stb[ci0 + ci];
            s_in[ci][r][c] = v;
        }
        // ---- load weight tile, duplicated for f32x2 broadcast ----
        for (int e = tid; e < CI_CHUNK * KK_ * 64; e += 256) {
            int co_l = e & 63;
            int t    = e >> 6;
            int k    = t % 9;
            int ci   = t / 9;
            float wv = wt[(((ci0 + ci) * 9 + k) << 8) + co0 + co_l];
            s_w[ci][k][co_l] = make_float2(wv, wv);
        }
        __syncthreads();

        // ---- compute (ci loop kept rolled: hot body fits I$) ----
        #pragma unroll 1
        for (int ci = 0; ci < CI_CHUNK; ci++) {
            #pragma unroll
            for (int kw = 0; kw < 3; kw++) {
                const float* sp = &s_in[ci][row4][col + kw];
                float f0 = sp[0 * SW_IN], f1 = sp[1 * SW_IN], f2 = sp[2 * SW_IN];
                float f3 = sp[3 * SW_IN], f4 = sp[4 * SW_IN], f5 = sp[5 * SW_IN];
                unsigned long long P0 = pack2(f0, f1);
                unsigned long long P1 = pack2(f1, f2);
                unsigned long long P2 = pack2(f2, f3);
                unsigned long long P3 = pack2(f3, f4);
                unsigned long long P4 = pack2(f4, f5);
                unsigned long long Plo[3] = {P0, P1, P2};
                unsigned long long Phi[3] = {P2, P3, P4};
                #pragma unroll
                for (int kh = 0; kh < 3; kh++) {
                    const unsigned long long* wrow =
                        reinterpret_cast<const unsigned long long*>(&s_w[ci][kh * 3 + kw][0])
                        + (co_sub << 4);
                    #pragma unroll
                    for (int j = 0; j < 16; j++) {
                        unsigned long long w2 = wrow[j];   // warp-uniform broadcast
                        fma2(acc[j][0], w2, Plo[kh]);
                        fma2(acc[j][1], w2, Phi[kh]);
                    }
                }
            }
        }
        __syncthreads();
    }

    // ---- epilogue: demod scale + noise + leaky relu ----
    float nz[4];
    #pragma unroll
    for (int p = 0; p < 4; p++)
        nz[p] = noise[(b << 12) + ((tile_r + row4 + p) << 6) + (tile_c + col)];

    #pragma unroll
    for (int j = 0; j < 16; j++) {
        int co    = co0 + (co_sub << 4) + j;
        float dm  = demod[(b << 8) + co];
        float nwv = nw[co];
        float v0, v1, v2, v3;
        unpack2(acc[j][0], v0, v1);
        unpack2(acc[j][1], v2, v3);
        float vs[4] = {v0, v1, v2, v3};
        int base = ((b << 8) + co) << 12;
        #pragma unroll
        for (int p = 0; p < 4; p++) {
            float v = vs[p] * dm + nwv * nz[p];
            v = (v > 0.f) ? v : 0.2f * v;
            out[base + ((tile_r + row4 + p) << 6) + (tile_c + col)] = v;
        }
    }
}

// ---------------- launcher ----------------------------------------------------
extern "C" void kernel_launch(void* const* d_in, const int* in_sizes, int n_in,
                              void* d_out, int out_size) {
    const float* x       = (const float*)d_in[0];
    const float* w1      = (const float*)d_in[1];
    const float* w2      = (const float*)d_in[2];
    const float* noise1  = (const float*)d_in[3];
    const float* noise2  = (const float*)d_in[4];
    const float* s1_w    = (const float*)d_in[5];
    const float* s1_b    = (const float*)d_in[6];
    const float* conv1_w = (const float*)d_in[7];
    const float* nw1     = (const float*)d_in[8];
    const float* s2_w    = (const float*)d_in[9];
    const float* s2_b    = (const float*)d_in[10];
    const float* conv2_w = (const float*)d_in[11];
    const float* nw2     = (const float*)d_in[12];
    float* out = (float*)d_out;

    float *p_h, *p_w1t, *p_w2t, *p_st1, *p_st2, *p_dm1, *p_dm2;
    cudaGetSymbolAddress((void**)&p_h,   g_h);
    cudaGetSymbolAddress((void**)&p_w1t, g_w1t);
    cudaGetSymbolAddress((void**)&p_w2t, g_w2t);
    cudaGetSymbolAddress((void**)&p_st1, g_style1);
    cudaGetSymbolAddress((void**)&p_st2, g_style2);
    cudaGetSymbolAddress((void**)&p_dm1, g_demod1);
    cudaGetSymbolAddress((void**)&p_dm2, g_demod2);

    const int nwt = C_ * C_ * KK_;             // 589824
    transpose_w_kernel<<<(nwt + 255) / 256, 256>>>(conv1_w, p_w1t);
    transpose_w_kernel<<<(nwt + 255) / 256, 256>>>(conv2_w, p_w2t);

    style_kernel<<<(B_ * C_) / 8, 256>>>(w1, s1_w, s1_b, p_st1);
    style_kernel<<<(B_ * C_) / 8, 256>>>(w2, s2_w, s2_b, p_st2);

    demod_kernel<<<B_, 256>>>(p_w1t, p_st1, p_dm1);
    demod_kernel<<<B_, 256>>>(p_w2t, p_st2, p_dm2);

    dim3 grid(16, 4, 16);   // (4x4 spatial tiles, 4 co-tiles, 16 batches)
    conv_mod_kernel<<<grid, 256>>>(x,   p_w1t, p_st1, p_dm1, nw1, noise1, p_h);
    conv_mod_kernel<<<grid, 256>>>(p_h, p_w2t, p_st2, p_dm2, nw2, noise2, out);
}

// round 3
// speedup vs baseline: 1.0014x; 1.0014x over previous
#include <cuda_runtime.h>
#include <cstdint>

// Problem constants
#define B_   16
#define C_   256      // Cin == Cout == 256
#define S_   512      // style dim
#define HW_  64
#define KK_  9        // 3x3
#define PIX_ (HW_*HW_)        // 4096
#define STYLE_SCALE 0.03125f  // 2^-0.5 * 512^-0.5 = 1/32
#define EPS_ 1e-8f

// ---------------- scratch (device globals: allocation-free rule) -------------
__device__ float g_h[B_ * C_ * PIX_];        // intermediate activation (67MB)
__device__ float g_w1t[C_ * C_ * KK_];       // conv1 weights transposed [ci][k][co]
__device__ float g_w2t[C_ * C_ * KK_];
__device__ float g_style1[B_ * C_];
__device__ float g_style2[B_ * C_];
__device__ float g_demod1[B_ * C_];
__device__ float g_demod2[B_ * C_];

// ---------------- f32x2 helpers ---------------------------------------------
__device__ __forceinline__ void fma2(unsigned long long &d, unsigned long long a,
                                     unsigned long long b) {
    asm("fma.rn.f32x2 %0, %1, %2, %0;" : "+l"(d) : "l"(a), "l"(b));
}
__device__ __forceinline__ unsigned long long pack2(float lo, float hi) {
    unsigned long long r;
    asm("mov.b64 %0, {%1, %2};" : "=l"(r) : "f"(lo), "f"(hi));
    return r;
}
__device__ __forceinline__ void unpack2(unsigned long long v, float &lo, float &hi) {
    asm("mov.b64 {%0, %1}, %2;" : "=f"(lo), "=f"(hi) : "l"(v));
}

// ---------------- prep: transpose weights [co][ci][k] -> [ci*9+k][co] --------
__global__ void transpose_w_kernel(const float* __restrict__ w, float* __restrict__ wt) {
    int e = blockIdx.x * 256 + threadIdx.x;           // e = (ci*9+k)*256 + co
    if (e >= C_ * C_ * KK_) return;
    int co   = e & 255;
    int rest = e >> 8;                                // ci*9 + k
    int k    = rest % 9;
    int ci   = rest / 9;
    wt[e] = w[co * (C_ * KK_) + ci * KK_ + k];
}

// ---------------- prep: style = (w * scale) @ sw^T + sb ----------------------
// one warp per (b, c) output; lanes stride over style dim
__global__ void style_kernel(const float* __restrict__ wvec,   // [B, S]
                             const float* __restrict__ sw,     // [C, S]
                             const float* __restrict__ sb,     // [C]
                             float* __restrict__ style) {      // [B, C]
    int gw   = blockIdx.x * 8 + (threadIdx.x >> 5);  // global warp id
    int lane = threadIdx.x & 31;
    if (gw >= B_ * C_) return;
    int b = gw >> 8;          // /C_
    int c = gw & 255;
    const float* wv = wvec + b * S_;
    const float* sr = sw + c * S_;
    float sum = 0.f;
    #pragma unroll 4
    for (int s = lane; s < S_; s += 32) sum += wv[s] * sr[s];
    #pragma unroll
    for (int off = 16; off > 0; off >>= 1)
        sum += __shfl_down_sync(0xffffffffu, sum, off);
    if (lane == 0) style[b * C_ + c] = sum * STYLE_SCALE + sb[c];
}

// ---------------- prep: demod = rsqrt(sum_ci style^2 * sum_k w^2 + eps) ------
// one block per batch; thread = co; coalesced reads of transposed weights
__global__ void demod_kernel(const float* __restrict__ wt,     // [C*9, C]
                             const float* __restrict__ style,  // [B, C]
                             float* __restrict__ demod) {      // [B, C]
    __shared__ float st2[C_];
    int b  = blockIdx.x;
    int co = threadIdx.x;
    float s = style[b * C_ + co];
    st2[co] = s * s;
    __syncthreads();
    float acc = 0.f;
    int ci = 0, kc = 0;
    #pragma unroll 8
    for (int idx = 0; idx < C_ * KK_; idx++) {
        float v = wt[idx * C_ + co];
        acc += st2[ci] * v * v;
        if (++kc == 9) { kc = 0; ci++; }
    }
    demod[b * C_ + co] = rsqrtf(acc + EPS_);
}

// ---------------- main conv: modulated 3x3 conv + noise + leaky relu ---------
// grid: (16 spatial tiles, 4 co-tiles, 16 batches); block 256 threads
// thread: 16 cout x 4 pixels (column of 4 rows), f32x2-packed accumulators
#define CI_CHUNK 8
#define SW_IN 20   // padded row stride (conflict-free for 2 row-groups x 16 cols)

__global__ __launch_bounds__(256, 2)
void conv_mod_kernel(const float* __restrict__ x,      // [B, C, 64, 64]
                     const float* __restrict__ wt,     // [C*9, C] transposed
                     const float* __restrict__ style,  // [B, C]
                     const float* __restrict__ demod,  // [B, C]
                     const float* __restrict__ nw,     // [C]
                     const float* __restrict__ noise,  // [B, 1, 64, 64]
                     float* __restrict__ out) {        // [B, C, 64, 64]
    __shared__ float  s_in[CI_CHUNK][18][SW_IN];
    __shared__ float2 s_w[CI_CHUNK][KK_][64];

    const int tid    = threadIdx.x;
    const int b      = blockIdx.z;
    const int co0    = blockIdx.y << 6;                 // * 64
    const int tile_r = (blockIdx.x >> 2) << 4;          // * 16
    const int tile_c = (blockIdx.x & 3) << 4;

    const int co_sub = tid >> 6;                        // 0..3 (uniform per warp-pair)
    const int pg     = tid & 63;
    const int col    = pg & 15;                         // 0..15
    const int row4   = (pg >> 4) << 2;                  // 0,4,8,12

    unsigned long long acc[16][2];
    #pragma unroll
    for (int j = 0; j < 16; j++) { acc[j][0] = 0ULL; acc[j][1] = 0ULL; }

    const float* xb  = x + ((size_t)b << 20);           // b * C_*PIX_
    const float* stb = style + (b << 8);

    for (int ci0 = 0; ci0 < C_; ci0 += CI_CHUNK) {
        // ---- load style-modulated input tile (with halo, zero-padded) ----
        for (int e = tid; e < CI_CHUNK * 18 * 18; e += 256) {
            int ci  = e / 324;
            int rem = e - ci * 324;
            int r   = rem / 18;
            int c   = rem - r * 18;
            int gr  = tile_r + r - 1;
            int gc  = tile_c + c - 1;
            float v = 0.f;
            if ((unsigned)gr < 64u && (unsigned)gc < 64u)
                v = xb[((ci0 + ci) << 12) + (gr << 6) + gc] * stb[ci0 + ci];
            s_in[ci][r][c] = v;
        }
        // ---- load weight tile, duplicated for f32x2 broadcast ----
        for (int e = tid; e < CI_CHUNK * KK_ * 64; e += 256) {
            int co_l = e & 63;
            int t    = e >> 6;
            int k    = t % 9;
            int ci   = t / 9;
            float wv = wt[(((ci0 + ci) * 9 + k) << 8) + co0 + co_l];
            s_w[ci][k][co_l] = make_float2(wv, wv);
        }
        __syncthreads();

        // ---- compute (ci loop kept rolled: hot body fits I$) ----
        #pragma unroll 1
        for (int ci = 0; ci < CI_CHUNK; ci++) {
            #pragma unroll
            for (int kw = 0; kw < 3; kw++) {
                const float* sp = &s_in[ci][row4][col + kw];
                float f0 = sp[0 * SW_IN], f1 = sp[1 * SW_IN], f2 = sp[2 * SW_IN];
                float f3 = sp[3 * SW_IN], f4 = sp[4 * SW_IN], f5 = sp[5 * SW_IN];
                unsigned long long P0 = pack2(f0, f1);
                unsigned long long P1 = pack2(f1, f2);
                unsigned long long P2 = pack2(f2, f3);
                unsigned long long P3 = pack2(f3, f4);
                unsigned long long P4 = pack2(f4, f5);
                unsigned long long Plo[3] = {P0, P1, P2};
                unsigned long long Phi[3] = {P2, P3, P4};
                #pragma unroll
                for (int kh = 0; kh < 3; kh++) {
                    const unsigned long long* wrow =
                        reinterpret_cast<const unsigned long long*>(&s_w[ci][kh * 3 + kw][0])
                        + (co_sub << 4);
                    #pragma unroll
                    for (int j = 0; j < 16; j++) {
                        unsigned long long w2 = wrow[j];   // warp-uniform broadcast
                        fma2(acc[j][0], w2, Plo[kh]);
                        fma2(acc[j][1], w2, Phi[kh]);
                    }
                }
            }
        }
        __syncthreads();
    }

    // ---- epilogue: demod scale + noise + leaky relu ----
    float nz[4];
    #pragma unroll
    for (int p = 0; p < 4; p++)
        nz[p] = noise[(b << 12) + ((tile_r + row4 + p) << 6) + (tile_c + col)];

    #pragma unroll
    for (int j = 0; j < 16; j++) {
        int co    = co0 + (co_sub << 4) + j;
        float dm  = demod[(b << 8) + co];
        float nwv = nw[co];
        float v0, v1, v2, v3;
        unpack2(acc[j][0], v0, v1);
        unpack2(acc[j][1], v2, v3);
        float vs[4] = {v0, v1, v2, v3};
        int base = ((b << 8) + co) << 12;
        #pragma unroll
        for (int p = 0; p < 4; p++) {
            float v = vs[p] * dm + nwv * nz[p];
            v = (v > 0.f) ? v : 0.2f * v;
            out[base + ((tile_r + row4 + p) << 6) + (tile_c + col)] = v;
        }
    }
}

// ---------------- launcher ----------------------------------------------------
extern "C" void kernel_launch(void* const* d_in, const int* in_sizes, int n_in,
                              void* d_out, int out_size) {
    const float* x       = (const float*)d_in[0];
    const float* w1      = (const float*)d_in[1];
    const float* w2      = (const float*)d_in[2];
    const float* noise1  = (const float*)d_in[3];
    const float* noise2  = (const float*)d_in[4];
    const float* s1_w    = (const float*)d_in[5];
    const float* s1_b    = (const float*)d_in[6];
    const float* conv1_w = (const float*)d_in[7];
    const float* nw1     = (const float*)d_in[8];
    const float* s2_w    = (const float*)d_in[9];
    const float* s2_b    = (const float*)d_in[10];
    const float* conv2_w = (const float*)d_in[11];
    const float* nw2     = (const float*)d_in[12];
    float* out = (float*)d_out;

    float *p_h, *p_w1t, *p_w2t, *p_st1, *p_st2, *p_dm1, *p_dm2;
    cudaGetSymbolAddress((void**)&p_h,   g_h);
    cudaGetSymbolAddress((void**)&p_w1t, g_w1t);
    cudaGetSymbolAddress((void**)&p_w2t, g_w2t);
    cudaGetSymbolAddress((void**)&p_st1, g_style1);
    cudaGetSymbolAddress((void**)&p_st2, g_style2);
    cudaGetSymbolAddress((void**)&p_dm1, g_demod1);
    cudaGetSymbolAddress((void**)&p_dm2, g_demod2);

    const int nwt = C_ * C_ * KK_;             // 589824
    transpose_w_kernel<<<(nwt + 255) / 256, 256>>>(conv1_w, p_w1t);
    transpose_w_kernel<<<(nwt + 255) / 256, 256>>>(conv2_w, p_w2t);

    style_kernel<<<(B_ * C_) / 8, 256>>>(w1, s1_w, s1_b, p_st1);
    style_kernel<<<(B_ * C_) / 8, 256>>>(w2, s2_w, s2_b, p_st2);

    demod_kernel<<<B_, 256>>>(p_w1t, p_st1, p_dm1);
    demod_kernel<<<B_, 256>>>(p_w2t, p_st2, p_dm2);

    dim3 grid(16, 4, 16);   // (4x4 spatial tiles, 4 co-tiles, 16 batches)
    conv_mod_kernel<<<grid, 256>>>(x,   p_w1t, p_st1, p_dm1, nw1, noise1, p_h);
    conv_mod_kernel<<<grid, 256>>>(p_h, p_w2t, p_st2, p_dm2, nw2, noise2, out);
}

// round 6
// speedup vs baseline: 6.1386x; 6.1301x over previous
#include <cuda_runtime.h>
#include <cuda_fp16.h>
#include <cstdint>

#define B_ 16
#define C_ 256
#define S_ 512
#define P_ 66
#define STYLE_SCALE 0.03125f
#define EPS_ 1e-8f
#define XT_ELEMS ((size_t)B_ * P_ * P_ * C_)

// ---------------- device scratch ----------------
__device__ __half g_xt[XT_ELEMS];          // style1-scaled x, NHWC padded, fp16
__device__ __half g_ht[XT_ELEMS];          // style2-scaled h, NHWC padded, fp16
__device__ __half g_wf[2][9][C_][C_];      // weights fp16 [conv][tap][cout][cin]
__device__ float  g_wsq[2][C_][C_];        // sum_k w^2
__device__ float  g_style[2][B_][C_];
__device__ float  g_demod[2][B_][C_];

// ---------------- PTX helpers ----------------
__device__ __forceinline__ uint32_t smem_u32(const void* p) {
    uint32_t a;
    asm("{ .reg .u64 t; cvta.to.shared.u64 t, %1; cvt.u32.u64 %0, t; }" : "=r"(a) : "l"(p));
    return a;
}
__device__ __forceinline__ void cp16(uint32_t s, const void* g) {
    asm volatile("cp.async.cg.shared.global [%0], [%1], 16;" :: "r"(s), "l"(g));
}
__device__ __forceinline__ void cp_commit() { asm volatile("cp.async.commit_group;" ::: "memory"); }
__device__ __forceinline__ void cp_wait3()  { asm volatile("cp.async.wait_group 3;" ::: "memory"); }
__device__ __forceinline__ void ldmx4(uint32_t* r, uint32_t a) {
    asm volatile("ldmatrix.sync.aligned.m8n8.x4.shared.b16 {%0,%1,%2,%3}, [%4];"
                 : "=r"(r[0]), "=r"(r[1]), "=r"(r[2]), "=r"(r[3]) : "r"(a));
}
__device__ __forceinline__ void mma16816(float* d, const uint32_t* a, const uint32_t* b) {
    asm volatile(
        "mma.sync.aligned.m16n8k16.row.col.f32.f16.f16.f32 "
        "{%0,%1,%2,%3}, {%4,%5,%6,%7}, {%8,%9}, {%0,%1,%2,%3};"
        : "+f"(d[0]), "+f"(d[1]), "+f"(d[2]), "+f"(d[3])
        : "r"(a[0]), "r"(a[1]), "r"(a[2]), "r"(a[3]), "r"(b[0]), "r"(b[1]));
}

// ---------------- prep: weights -> fp16 [tap][cout][cin] + wsq ----------------
__global__ void wprep_kernel(const float* __restrict__ w1, const float* __restrict__ w2) {
    int idx = blockIdx.x * 256 + threadIdx.x;
    if (idx >= 2 * C_ * C_) return;
    int cv = idx >> 16, co = (idx >> 8) & 255, ci = idx & 255;
    const float* w = cv ? w2 : w1;
    float sq = 0.f;
    #pragma unroll
    for (int k = 0; k < 9; k++) {
        float v = w[(co * C_ + ci) * 9 + k];
        sq += v * v;
        g_wf[cv][k][co][ci] = __float2half(v);
    }
    g_wsq[cv][co][ci] = sq;
}

// ---------------- prep: style ----------------
__global__ void style_kernel(const float* __restrict__ w1v, const float* __restrict__ w2v,
                             const float* __restrict__ s1w, const float* __restrict__ s1b,
                             const float* __restrict__ s2w, const float* __restrict__ s2b) {
    int gw = blockIdx.x * 8 + (threadIdx.x >> 5), lane = threadIdx.x & 31;
    int cv = gw >> 12, b = (gw >> 8) & 15, c = gw & 255;
    const float* wv = (cv ? w2v : w1v) + b * S_;
    const float* sr = (cv ? s2w : s1w) + c * S_;
    float sum = 0.f;
    #pragma unroll 4
    for (int s = lane; s < S_; s += 32) sum += wv[s] * sr[s];
    #pragma unroll
    for (int o = 16; o > 0; o >>= 1) sum += __shfl_down_sync(0xffffffffu, sum, o);
    if (lane == 0) g_style[cv][b][c] = sum * STYLE_SCALE + (cv ? s2b : s1b)[c];
}

// ---------------- prep: demod ----------------
__global__ void demod_kernel() {
    int gw = blockIdx.x * 8 + (threadIdx.x >> 5), lane = threadIdx.x & 31;
    int cv = gw >> 12, b = (gw >> 8) & 15, co = gw & 255;
    float sum = 0.f;
    #pragma unroll 4
    for (int ci = lane; ci < C_; ci += 32) {
        float s = g_style[cv][b][ci];
        sum += s * s * g_wsq[cv][co][ci];
    }
    #pragma unroll
    for (int o = 16; o > 0; o >>= 1) sum += __shfl_down_sync(0xffffffffu, sum, o);
    if (lane == 0) g_demod[cv][b][co] = rsqrtf(sum + EPS_);
}

// ---------------- prep: zero halo ring of both padded buffers ----------------
__global__ void halo_kernel() {
    int e = blockIdx.x * 256 + threadIdx.x;
    if (e >= B_ * 260 * C_) return;
    int ci = e & 255, t = e >> 8, i = t % 260, b = t / 260;
    int py, px;
    if (i < 66)       { py = 0;       px = i; }
    else if (i < 132) { py = 65;      px = i - 66; }
    else if (i < 196) { py = i - 131; px = 0; }
    else              { py = i - 195; px = 65; }
    size_t a = (((size_t)b * P_ + py) * P_ + px) * C_ + ci;
    g_xt[a] = __float2half(0.f);
    g_ht[a] = __float2half(0.f);
}

// ---------------- prep: x (NCHW) -> style1-scaled padded NHWC fp16 ----------------
__global__ void xprep_kernel(const float* __restrict__ x) {
    __shared__ float t[64][65];
    __shared__ float st[64];
    int tid = threadIdx.x, b = blockIdx.z, py = blockIdx.y, c0 = blockIdx.x << 6;
    if (tid < 64) st[tid] = g_style[0][b][c0 + tid];
    #pragma unroll 4
    for (int i = 0; i < 16; i++) {
        int ci = (i << 2) + (tid >> 6), px = tid & 63;
        t[ci][px] = x[(((size_t)b * C_ + c0 + ci) << 12) + (py << 6) + px];
    }
    __syncthreads();
    #pragma unroll 4
    for (int i = 0; i < 16; i++) {
        int px = (i << 2) + (tid >> 6), ci = tid & 63;
        float v = t[ci][px] * st[ci];
        size_t a = (((size_t)b * P_ + py + 1) * P_ + px + 1) * C_ + c0 + ci;
        g_xt[a] = __float2half(v);
    }
}

// ---------------- main conv: implicit GEMM via mma.sync fp16 ----------------
// CTA 256 thr: M=128 couts x N=128 pixels (2 image rows), K=2304 = 144 k16 steps
// 4-stage cp.async pipeline, 8KB/stage (A 4KB + B 4KB)
#define NSTEP 144
#define STAGE_BYTES 8192
#define SMEM_CONV 34816   // max(4*8192 pipeline, 128*272 epilogue transpose)

__global__ __launch_bounds__(256, 2)
void conv_hmma_kernel(const __half* __restrict__ xt, int wsel,
                      const float* __restrict__ nw,
                      const float* __restrict__ noise, int mode,
                      __half* __restrict__ o_h, float* __restrict__ outp) {
    extern __shared__ __align__(16) char smem_raw[];
    const uint32_t sb = smem_u32(smem_raw);

    const int tid = threadIdx.x;
    const int wid = tid >> 5, lane = tid & 31;
    const int warp_m = wid & 3, warp_n = wid >> 2;
    const int n0 = blockIdx.x << 7;       // pixel tile base (0..3968)
    const int co0 = blockIdx.y << 7;      // cout tile base
    const int b = blockIdx.z;
    const int row0 = n0 >> 6;             // image row base

    const int lrow = tid >> 1, lhalf = tid & 1;

    // per-lane ldmatrix offsets (within stage slot)
    // A: matrices (m0-7,k0),(m8-15,k0),(m0-7,k8),(m8-15,k8)
    const int a_min  = (lane & 7) + ((lane >> 3) & 1) * 8;
    const int a_koff = (lane >> 4) << 4;
    // B: matrices (n0-7,k0),(n0-7,k8),(n8-15,k0),(n8-15,k8)
    const int b_nin  = ((lane >> 4) << 3) + (lane & 7);
    const int b_koff = ((lane >> 3) & 1) << 4;

    float acc[2][8][4];
    #pragma unroll
    for (int i = 0; i < 2; i++)
        #pragma unroll
        for (int j = 0; j < 8; j++)
            #pragma unroll
            for (int r = 0; r < 4; r++) acc[i][j][r] = 0.f;

    auto load_stage = [&](int s) {
        if (s < NSTEP) {
            const uint32_t slot = sb + (s & 3) * STAGE_BYTES;
            const int tap = s >> 4, cin0 = (s & 15) << 4;
            const int dy = tap / 3, dx = tap - dy * 3;
            // A: weights [co0+lrow][cin0 + lhalf*8]
            cp16(slot + lrow * 32 + lhalf * 16,
                 &g_wf[wsel][tap][co0 + lrow][cin0 + lhalf * 8]);
            // B: activations pixel lrow
            const int py = row0 + (lrow >> 6) + dy;
            const int px = (lrow & 63) + dx;
            cp16(slot + 4096 + lrow * 32 + lhalf * 16,
                 xt + ((((size_t)b * P_ + py) * P_ + px) << 8) + cin0 + lhalf * 8);
        }
        cp_commit();
    };

    load_stage(0); load_stage(1); load_stage(2);

    #pragma unroll 1
    for (int s = 0; s < NSTEP; s++) {
        load_stage(s + 3);
        cp_wait3();
        __syncthreads();
        const uint32_t slot = sb + (s & 3) * STAGE_BYTES;
        const uint32_t abase = slot + (warp_m * 32 + a_min) * 32 + a_koff;
        const uint32_t bbase = slot + 4096 + (warp_n * 64 + b_nin) * 32 + b_koff;

        uint32_t a[2][4], bf[8][2];
        #pragma unroll
        for (int f = 0; f < 2; f++) ldmx4(a[f], abase + f * 16 * 32);
        #pragma unroll
        for (int g = 0; g < 4; g++) {
            uint32_t r[4];
            ldmx4(r, bbase + g * 16 * 32);
            bf[2 * g][0] = r[0]; bf[2 * g][1] = r[1];
            bf[2 * g + 1][0] = r[2]; bf[2 * g + 1][1] = r[3];
        }
        #pragma unroll
        for (int im = 0; im < 2; im++)
            #pragma unroll
            for (int in = 0; in < 8; in++)
                mma16816(acc[im][in], a[im], bf[in]);
        __syncthreads();
    }

    // ---------------- epilogue ----------------
    const int qm = lane >> 2;            // 0..7
    const int qn = (lane & 3) << 1;      // 0,2,4,6

    if (mode == 1) {
        // fp32 NCHW output, float2 packed (n, n+1)
        #pragma unroll
        for (int im = 0; im < 2; im++) {
            #pragma unroll
            for (int rr = 0; rr < 2; rr++) {     // rr=0 -> c0/c1 (m), rr=1 -> c2/c3 (m+8)
                const int m = co0 + warp_m * 32 + im * 16 + qm + rr * 8;
                const float dm = g_demod[wsel][b][m];
                const float nwv = nw[m];
                float* ob = outp + (((size_t)b << 8) + m) * 4096;
                #pragma unroll
                for (int in = 0; in < 8; in++) {
                    const int n = n0 + warp_n * 64 + in * 8 + qn;
                    float v0 = acc[im][in][rr * 2 + 0] * dm + nwv * noise[((size_t)b << 12) + n];
                    float v1 = acc[im][in][rr * 2 + 1] * dm + nwv * noise[((size_t)b << 12) + n + 1];
                    v0 = v0 > 0.f ? v0 : 0.2f * v0;
                    v1 = v1 > 0.f ? v1 : 0.2f * v1;
                    *reinterpret_cast<float2*>(ob + n) = make_float2(v0, v1);
                }
            }
        }
    } else {
        // h: demod+noise+leaky, *style2, fp16, via smem transpose -> NHWC padded
        __half* hs = reinterpret_cast<__half*>(smem_raw);   // [128 n][stride 136]
        #pragma unroll
        for (int im = 0; im < 2; im++) {
            #pragma unroll
            for (int rr = 0; rr < 2; rr++) {
                const int ml = warp_m * 32 + im * 16 + qm + rr * 8;
                const int m = co0 + ml;
                const float dm = g_demod[wsel][b][m];
                const float nwv = nw[m];
                const float sty = g_style[1][b][m];
                #pragma unroll
                for (int in = 0; in < 8; in++) {
                    const int nl = warp_n * 64 + in * 8 + qn;
                    const int n = n0 + nl;
                    float v0 = acc[im][in][rr * 2 + 0] * dm + nwv * noise[((size_t)b << 12) + n];
                    float v1 = acc[im][in][rr * 2 + 1] * dm + nwv * noise[((size_t)b << 12) + n + 1];
                    v0 = (v0 > 0.f ? v0 : 0.2f * v0) * sty;
                    v1 = (v1 > 0.f ? v1 : 0.2f * v1) * sty;
                    hs[nl * 136 + ml] = __float2half(v0);
                    hs[(nl + 1) * 136 + ml] = __float2half(v1);
                }
            }
        }
        __syncthreads();
        // coalesced writeback: thread -> 128B (64 fp16) of one pixel row
        const int nl = tid >> 1, half = tid & 1;
        const int pix = n0 + nl;
        const int py = (pix >> 6) + 1, px = (pix & 63) + 1;
        const uint4* src = reinterpret_cast<const uint4*>(hs + nl * 136 + half * 64);
        uint4* dst = reinterpret_cast<uint4*>(
            o_h + ((((size_t)b * P_ + py) * P_ + px) << 8) + co0 + half * 64);
        #pragma unroll
        for (int i = 0; i < 8; i++) dst[i] = src[i];
    }
}

// ---------------- launcher ----------------
extern "C" void kernel_launch(void* const* d_in, const int* in_sizes, int n_in,
                              void* d_out, int out_size) {
    const float* x       = (const float*)d_in[0];
    const float* w1      = (const float*)d_in[1];
    const float* w2      = (const float*)d_in[2];
    const float* noise1  = (const float*)d_in[3];
    const float* noise2  = (const float*)d_in[4];
    const float* s1_w    = (const float*)d_in[5];
    const float* s1_b    = (const float*)d_in[6];
    const float* conv1_w = (const float*)d_in[7];
    const float* nw1     = (const float*)d_in[8];
    const float* s2_w    = (const float*)d_in[9];
    const float* s2_b    = (const float*)d_in[10];
    const float* conv2_w = (const float*)d_in[11];
    const float* nw2     = (const float*)d_in[12];
    float* out = (float*)d_out;

    __half *p_xt, *p_ht;
    cudaGetSymbolAddress((void**)&p_xt, g_xt);
    cudaGetSymbolAddress((void**)&p_ht, g_ht);

    wprep_kernel<<<(2 * C_ * C_ + 255) / 256, 256>>>(conv1_w, conv2_w);
    style_kernel<<<1024, 256>>>(w1, w2, s1_w, s1_b, s2_w, s2_b);
    halo_kernel<<<(B_ * 260 * C_ + 255) / 256, 256>>>();
    xprep_kernel<<<dim3(4, 64, 16), 256>>>(x);
    demod_kernel<<<1024, 256>>>();

    dim3 grid(32, 2, 16);
    conv_hmma_kernel<<<grid, 256, SMEM_CONV>>>(p_xt, 0, nw1, noise1, 0, p_ht, nullptr);
    conv_hmma_kernel<<<grid, 256, SMEM_CONV>>>(p_ht, 1, nw2, noise2, 1, nullptr, out);
}

// round 9
// speedup vs baseline: 9.8917x; 1.6114x over previous
#include <cuda_runtime.h>
#include <cuda_fp16.h>
#include <cstdint>

#define B_ 16
#define C_ 256
#define S_ 512
#define P_ 66
#define STYLE_SCALE 0.03125f
#define EPS_ 1e-8f
#define XT_ELEMS ((size_t)B_ * P_ * P_ * C_)

// ---------------- device scratch ----------------
__device__ __half g_xt[XT_ELEMS];            // style1-scaled x, NHWC padded, fp16
__device__ __half g_ht[XT_ELEMS];            // style2-scaled h, NHWC padded, fp16
__device__ __half g_wf[2][9][16][C_][16];    // weights fp16 [conv][tap][cin16][cout][cin&15]
__device__ float  g_wsq[2][C_][C_];
__device__ float  g_style[2][B_][C_];
__device__ float  g_demod[2][B_][C_];

// ---------------- PTX helpers ----------------
__device__ __forceinline__ uint32_t smem_u32(const void* p) {
    uint32_t a;
    asm("{ .reg .u64 t; cvta.to.shared.u64 t, %1; cvt.u32.u64 %0, t; }" : "=r"(a) : "l"(p));
    return a;
}
__device__ __forceinline__ void cp16(uint32_t s, const void* g) {
    asm volatile("cp.async.cg.shared.global [%0], [%1], 16;" :: "r"(s), "l"(g));
}
__device__ __forceinline__ void cp_commit() { asm volatile("cp.async.commit_group;" ::: "memory"); }
__device__ __forceinline__ void cp_wait1()  { asm volatile("cp.async.wait_group 1;" ::: "memory"); }
__device__ __forceinline__ void ldmx4(uint32_t* r, uint32_t a) {
    asm volatile("ldmatrix.sync.aligned.m8n8.x4.shared.b16 {%0,%1,%2,%3}, [%4];"
                 : "=r"(r[0]), "=r"(r[1]), "=r"(r[2]), "=r"(r[3]) : "r"(a));
}
__device__ __forceinline__ void mma16816(float* d, const uint32_t* a, const uint32_t* b) {
    asm volatile(
        "mma.sync.aligned.m16n8k16.row.col.f32.f16.f16.f32 "
        "{%0,%1,%2,%3}, {%4,%5,%6,%7}, {%8,%9}, {%0,%1,%2,%3};"
        : "+f"(d[0]), "+f"(d[1]), "+f"(d[2]), "+f"(d[3])
        : "r"(a[0]), "r"(a[1]), "r"(a[2]), "r"(a[3]), "r"(b[0]), "r"(b[1]));
}

// ---------------- prep kernels ----------------
__global__ void wprep_kernel(const float* __restrict__ w1, const float* __restrict__ w2) {
    int idx = blockIdx.x * 256 + threadIdx.x;
    if (idx >= 2 * C_ * C_) return;
    int cv = idx >> 16, co = (idx >> 8) & 255, ci = idx & 255;
    const float* w = cv ? w2 : w1;
    float sq = 0.f;
    #pragma unroll
    for (int k = 0; k < 9; k++) {
        float v = w[(co * C_ + ci) * 9 + k];
        sq += v * v;
        g_wf[cv][k][ci >> 4][co][ci & 15] = __float2half(v);
    }
    g_wsq[cv][co][ci] = sq;
}

__global__ void style_kernel(const float* __restrict__ w1v, const float* __restrict__ w2v,
                             const float* __restrict__ s1w, const float* __restrict__ s1b,
                             const float* __restrict__ s2w, const float* __restrict__ s2b) {
    int gw = blockIdx.x * 8 + (threadIdx.x >> 5), lane = threadIdx.x & 31;
    int cv = gw >> 12, b = (gw >> 8) & 15, c = gw & 255;
    const float* wv = (cv ? w2v : w1v) + b * S_;
    const float* sr = (cv ? s2w : s1w) + c * S_;
    float sum = 0.f;
    #pragma unroll 4
    for (int s = lane; s < S_; s += 32) sum += wv[s] * sr[s];
    #pragma unroll
    for (int o = 16; o > 0; o >>= 1) sum += __shfl_down_sync(0xffffffffu, sum, o);
    if (lane == 0) g_style[cv][b][c] = sum * STYLE_SCALE + (cv ? s2b : s1b)[c];
}

__global__ void demod_kernel() {
    int gw = blockIdx.x * 8 + (threadIdx.x >> 5), lane = threadIdx.x & 31;
    int cv = gw >> 12, b = (gw >> 8) & 15, co = gw & 255;
    float sum = 0.f;
    #pragma unroll 4
    for (int ci = lane; ci < C_; ci += 32) {
        float s = g_style[cv][b][ci];
        sum += s * s * g_wsq[cv][co][ci];
    }
    #pragma unroll
    for (int o = 16; o > 0; o >>= 1) sum += __shfl_down_sync(0xffffffffu, sum, o);
    if (lane == 0) g_demod[cv][b][co] = rsqrtf(sum + EPS_);
}

__global__ void halo_kernel() {
    int e = blockIdx.x * 256 + threadIdx.x;
    if (e >= B_ * 260 * C_) return;
    int ci = e & 255, t = e >> 8, i = t % 260, b = t / 260;
    int py, px;
    if (i < 66)       { py = 0;       px = i; }
    else if (i < 132) { py = 65;      px = i - 66; }
    else if (i < 196) { py = i - 131; px = 0; }
    else              { py = i - 195; px = 65; }
    size_t a = (((size_t)b * P_ + py) * P_ + px) * C_ + ci;
    g_xt[a] = __float2half(0.f);
    g_ht[a] = __float2half(0.f);
}

__global__ void xprep_kernel(const float* __restrict__ x) {
    __shared__ float t[64][65];
    __shared__ float st[64];
    int tid = threadIdx.x, b = blockIdx.z, py = blockIdx.y, c0 = blockIdx.x << 6;
    if (tid < 64) st[tid] = g_style[0][b][c0 + tid];
    #pragma unroll 4
    for (int i = 0; i < 16; i++) {
        int ci = (i << 2) + (tid >> 6), px = tid & 63;
        t[ci][px] = x[(((size_t)b * C_ + c0 + ci) << 12) + (py << 6) + px];
    }
    __syncthreads();
    #pragma unroll 4
    for (int i = 0; i < 16; i++) {
        int px = (i << 2) + (tid >> 6), ci = tid & 63;
        float v = t[ci][px] * st[ci];
        size_t a = (((size_t)b * P_ + py + 1) * P_ + px + 1) * C_ + c0 + ci;
        g_xt[a] = __float2half(v);
    }
}

// ---------------- main conv: implicit GEMM, tap-reuse stages ----------------
// CTA: M=128 couts x N=128 px (2 image rows). Stage = cin16 chunk: B slab of
// 4 haloed rows x 66 px (8448B) + A 9 taps x 128 co (36864B). 16 stages, 3 slots.
#define SLOT_B 8448
#define SLOT_A 36864
#define SLOT_BYTES (SLOT_B + SLOT_A)      // 45312
#define NSLOT 3
#define SMEM_CONV (NSLOT * SLOT_BYTES)    // 135936
#define NSTAGE 16

__device__ __forceinline__ uint32_t swz(int unit32, int half16) {
    // unit32: 32B-row index (px or co); half16: 0/16 byte offset (k-half)
    return (uint32_t)((unit32 * 32 + half16) ^ (((unit32 >> 2) & 1) << 4));
}

__global__ __launch_bounds__(256, 1)
void conv_hmma_kernel(const __half* __restrict__ xt, int wsel,
                      const float* __restrict__ nw,
                      const float* __restrict__ noise, int mode,
                      __half* __restrict__ o_h, float* __restrict__ outp) {
    extern __shared__ __align__(128) char smem_raw[];
    const uint32_t sb = smem_u32(smem_raw);

    const int tid = threadIdx.x;
    const int wid = tid >> 5, lane = tid & 31;
    const int warp_m = wid & 3, warp_n = wid >> 2;   // warp tile M=32, N=64 (one row)
    const int n0 = blockIdx.x << 7;                   // pixel tile base
    const int co0 = blockIdx.y << 7;
    const int b = blockIdx.z;
    const int r0 = blockIdx.x << 1;                   // padded-row base (img rows r0-1..r0+2)

    // ldmatrix lane mapping
    const int a_min  = (lane & 7) + ((lane >> 3) & 1) * 8;
    const int a_koff = (lane >> 4) << 4;
    const int b_nin  = ((lane >> 4) << 3) + (lane & 7);
    const int b_koff = ((lane >> 3) & 1) << 4;

    float acc[2][8][4];
    #pragma unroll
    for (int i = 0; i < 2; i++)
        #pragma unroll
        for (int j = 0; j < 8; j++)
            #pragma unroll
            for (int r = 0; r < 4; r++) acc[i][j][r] = 0.f;

    auto load_stage = [&](int s) {
        if (s < NSTAGE) {
            const uint32_t slot = sb + (s % NSLOT) * SLOT_BYTES;
            const int cin0 = s << 4;
            // B slab: 4 rows x 66 px x 2 16B-units = 528 units
            #pragma unroll
            for (int i = tid; i < 528; i += 256) {
                int row = i / 132, rem = i - row * 132;
                int px = rem >> 1, u = rem & 1;
                cp16(slot + row * 2112 + swz(px, u << 4),
                     xt + ((((size_t)b * P_ + r0 + row) * P_ + px) << 8) + cin0 + (u << 3));
            }
            // A: 9 taps x 128 co x 2 units = 2304 units (contiguous gmem)
            const __half* wbase = &g_wf[wsel][0][s][co0][0];   // [tap][16][C][16] stride
            #pragma unroll
            for (int i = tid; i < 2304; i += 256) {
                int tap = i >> 8, rem = i & 255;
                int co = rem >> 1, u = rem & 1;
                cp16(slot + SLOT_B + tap * 4096 + swz(co, u << 4),
                     wbase + (size_t)tap * (16 * C_ * 16) + co * 16 + u * 8);
            }
        }
        cp_commit();
    };

    load_stage(0); load_stage(1);

    #pragma unroll 1
    for (int s = 0; s < NSTAGE; s++) {
        cp_wait1();
        __syncthreads();
        load_stage(s + 2);
        const uint32_t slot = sb + (s % NSLOT) * SLOT_BYTES;
        const uint32_t aslot = slot + SLOT_B;

        #pragma unroll
        for (int tap = 0; tap < 9; tap++) {
            const int dy = tap / 3, dx = tap - dy * 3;
            uint32_t a[2][4];
            #pragma unroll
            for (int f = 0; f < 2; f++) {
                int co_l = warp_m * 32 + f * 16 + a_min;
                ldmx4(a[f], aslot + tap * 4096 + swz(co_l, a_koff));
            }
            uint32_t bf[8][2];
            const uint32_t rowbase = slot + (warp_n + dy) * 2112;
            #pragma unroll
            for (int g = 0; g < 4; g++) {
                int ppx = g * 16 + b_nin + dx;
                uint32_t r[4];
                ldmx4(r, rowbase + swz(ppx, b_koff));
                bf[2 * g][0] = r[0]; bf[2 * g][1] = r[1];
                bf[2 * g + 1][0] = r[2]; bf[2 * g + 1][1] = r[3];
            }
            #pragma unroll
            for (int im = 0; im < 2; im++)
                #pragma unroll
                for (int in = 0; in < 8; in++)
                    mma16816(acc[im][in], a[im], bf[in]);
        }
    }
    __syncthreads();   // protect smem reuse in epilogue

    // ---------------- epilogue ----------------
    const int qm = lane >> 2;
    const int qn = (lane & 3) << 1;

    if (mode == 1) {
        #pragma unroll
        for (int im = 0; im < 2; im++) {
            #pragma unroll
            for (int rr = 0; rr < 2; rr++) {
                const int m = co0 + warp_m * 32 + im * 16 + qm + rr * 8;
                const float dm = g_demod[wsel][b][m];
                const float nwv = nw[m];
                float* ob = outp + (((size_t)b << 8) + m) * 4096;
                #pragma unroll
                for (int in = 0; in < 8; in++) {
                    const int n = n0 + warp_n * 64 + in * 8 + qn;
                    float v0 = acc[im][in][rr * 2 + 0] * dm + nwv * noise[((size_t)b << 12) + n];
                    float v1 = acc[im][in][rr * 2 + 1] * dm + nwv * noise[((size_t)b << 12) + n + 1];
                    v0 = v0 > 0.f ? v0 : 0.2f * v0;
                    v1 = v1 > 0.f ? v1 : 0.2f * v1;
                    *reinterpret_cast<float2*>(ob + n) = make_float2(v0, v1);
                }
            }
        }
    } else {
        __half* hs = reinterpret_cast<__half*>(smem_raw);   // [128 n][stride 136]
        #pragma unroll
        for (int im = 0; im < 2; im++) {
            #pragma unroll
            for (int rr = 0; rr < 2; rr++) {
                const int ml = warp_m * 32 + im * 16 + qm + rr * 8;
                const int m = co0 + ml;
                const float dm = g_demod[wsel][b][m];
                const float nwv = nw[m];
                const float sty = g_style[1][b][m];
                #pragma unroll
                for (int in = 0; in < 8; in++) {
                    const int nl = warp_n * 64 + in * 8 + qn;
                    const int n = n0 + nl;
                    float v0 = acc[im][in][rr * 2 + 0] * dm + nwv * noise[((size_t)b << 12) + n];
                    float v1 = acc[im][in][rr * 2 + 1] * dm + nwv * noise[((size_t)b << 12) + n + 1];
                    v0 = (v0 > 0.f ? v0 : 0.2f * v0) * sty;
                    v1 = (v1 > 0.f ? v1 : 0.2f * v1) * sty;
                    hs[nl * 136 + ml] = __float2half(v0);
                    hs[(nl + 1) * 136 + ml] = __float2half(v1);
                }
            }
        }
        __syncthreads();
        const int nl = tid >> 1, half = tid & 1;
        const int pix = n0 + nl;
        const int py = (pix >> 6) + 1, px = (pix & 63) + 1;
        const uint4* src = reinterpret_cast<const uint4*>(hs + nl * 136 + half * 64);
        uint4* dst = reinterpret_cast<uint4*>(
            o_h + ((((size_t)b * P_ + py) * P_ + px) << 8) + co0 + half * 64);
        #pragma unroll
        for (int i = 0; i < 8; i++) dst[i] = src[i];
    }
}

// ---------------- launcher ----------------
extern "C" void kernel_launch(void* const* d_in, const int* in_sizes, int n_in,
                              void* d_out, int out_size) {
    const float* x       = (const float*)d_in[0];
    const float* w1      = (const float*)d_in[1];
    const float* w2      = (const float*)d_in[2];
    const float* noise1  = (const float*)d_in[3];
    const float* noise2  = (const float*)d_in[4];
    const float* s1_w    = (const float*)d_in[5];
    const float* s1_b    = (const float*)d_in[6];
    const float* conv1_w = (const float*)d_in[7];
    const float* nw1     = (const float*)d_in[8];
    const float* s2_w    = (const float*)d_in[9];
    const float* s2_b    = (const float*)d_in[10];
    const float* conv2_w = (const float*)d_in[11];
    const float* nw2     = (const float*)d_in[12];
    float* out = (float*)d_out;

    __half *p_xt, *p_ht;
    cudaGetSymbolAddress((void**)&p_xt, g_xt);
    cudaGetSymbolAddress((void**)&p_ht, g_ht);

    cudaFuncSetAttribute(conv_hmma_kernel,
                         cudaFuncAttributeMaxDynamicSharedMemorySize, SMEM_CONV);

    wprep_kernel<<<(2 * C_ * C_ + 255) / 256, 256>>>(conv1_w, conv2_w);
    style_kernel<<<1024, 256>>>(w1, w2, s1_w, s1_b, s2_w, s2_b);
    halo_kernel<<<(B_ * 260 * C_ + 255) / 256, 256>>>();
    xprep_kernel<<<dim3(4, 64, 16), 256>>>(x);
    demod_kernel<<<1024, 256>>>();

    dim3 grid(32, 2, 16);
    conv_hmma_kernel<<<grid, 256, SMEM_CONV>>>(p_xt, 0, nw1, noise1, 0, p_ht, nullptr);
    conv_hmma_kernel<<<grid, 256, SMEM_CONV>>>(p_ht, 1, nw2, noise2, 1, nullptr, out);
}

// round 10
// speedup vs baseline: 10.0494x; 1.0159x over previous
#include <cuda_runtime.h>
#include <cuda_fp16.h>
#include <cstdint>

#define B_ 16
#define C_ 256
#define S_ 512
#define P_ 66
#define STYLE_SCALE 0.03125f
#define EPS_ 1e-8f
#define XT_ELEMS ((size_t)B_ * P_ * P_ * C_)

// ---------------- device scratch ----------------
__device__ __half g_xt[XT_ELEMS];            // style1-scaled x, NHWC padded, fp16
__device__ __half g_ht[XT_ELEMS];            // style2-scaled h, NHWC padded, fp16
__device__ __half g_wf[2][9][16][C_][16];    // weights fp16 [conv][tap][cin16][cout][cin&15]
__device__ float  g_wsq[2][C_][C_];
__device__ float  g_style[2][B_][C_];
__device__ float  g_demod[2][B_][C_];

// ---------------- PTX helpers ----------------
__device__ __forceinline__ uint32_t smem_u32(const void* p) {
    uint32_t a;
    asm("{ .reg .u64 t; cvta.to.shared.u64 t, %1; cvt.u32.u64 %0, t; }" : "=r"(a) : "l"(p));
    return a;
}
__device__ __forceinline__ void cp16(uint32_t s, const void* g) {
    asm volatile("cp.async.cg.shared.global [%0], [%1], 16;" :: "r"(s), "l"(g));
}
__device__ __forceinline__ void cp_commit() { asm volatile("cp.async.commit_group;" ::: "memory"); }
__device__ __forceinline__ void cp_wait2()  { asm volatile("cp.async.wait_group 2;" ::: "memory"); }
__device__ __forceinline__ void ldmx4(uint32_t* r, uint32_t a) {
    asm volatile("ldmatrix.sync.aligned.m8n8.x4.shared.b16 {%0,%1,%2,%3}, [%4];"
                 : "=r"(r[0]), "=r"(r[1]), "=r"(r[2]), "=r"(r[3]) : "r"(a));
}
__device__ __forceinline__ void mma16816(float* d, const uint32_t* a, const uint32_t* b) {
    asm volatile(
        "mma.sync.aligned.m16n8k16.row.col.f32.f16.f16.f32 "
        "{%0,%1,%2,%3}, {%4,%5,%6,%7}, {%8,%9}, {%0,%1,%2,%3};"
        : "+f"(d[0]), "+f"(d[1]), "+f"(d[2]), "+f"(d[3])
        : "r"(a[0]), "r"(a[1]), "r"(a[2]), "r"(a[3]), "r"(b[0]), "r"(b[1]));
}

// ---------------- prep kernels ----------------
__global__ void wprep_kernel(const float* __restrict__ w1, const float* __restrict__ w2) {
    int idx = blockIdx.x * 256 + threadIdx.x;
    if (idx >= 2 * C_ * C_) return;
    int cv = idx >> 16, co = (idx >> 8) & 255, ci = idx & 255;
    const float* w = cv ? w2 : w1;
    float sq = 0.f;
    #pragma unroll
    for (int k = 0; k < 9; k++) {
        float v = w[(co * C_ + ci) * 9 + k];
        sq += v * v;
        g_wf[cv][k][ci >> 4][co][ci & 15] = __float2half(v);
    }
    g_wsq[cv][co][ci] = sq;
}

__global__ void style_kernel(const float* __restrict__ w1v, const float* __restrict__ w2v,
                             const float* __restrict__ s1w, const float* __restrict__ s1b,
                             const float* __restrict__ s2w, const float* __restrict__ s2b) {
    int gw = blockIdx.x * 8 + (threadIdx.x >> 5), lane = threadIdx.x & 31;
    int cv = gw >> 12, b = (gw >> 8) & 15, c = gw & 255;
    const float* wv = (cv ? w2v : w1v) + b * S_;
    const float* sr = (cv ? s2w : s1w) + c * S_;
    float sum = 0.f;
    #pragma unroll 4
    for (int s = lane; s < S_; s += 32) sum += wv[s] * sr[s];
    #pragma unroll
    for (int o = 16; o > 0; o >>= 1) sum += __shfl_down_sync(0xffffffffu, sum, o);
    if (lane == 0) g_style[cv][b][c] = sum * STYLE_SCALE + (cv ? s2b : s1b)[c];
}

__global__ void demod_kernel() {
    int gw = blockIdx.x * 8 + (threadIdx.x >> 5), lane = threadIdx.x & 31;
    int cv = gw >> 12, b = (gw >> 8) & 15, co = gw & 255;
    float sum = 0.f;
    #pragma unroll 4
    for (int ci = lane; ci < C_; ci += 32) {
        float s = g_style[cv][b][ci];
        sum += s * s * g_wsq[cv][co][ci];
    }
    #pragma unroll
    for (int o = 16; o > 0; o >>= 1) sum += __shfl_down_sync(0xffffffffu, sum, o);
    if (lane == 0) g_demod[cv][b][co] = rsqrtf(sum + EPS_);
}

__global__ void halo_kernel() {
    int e = blockIdx.x * 256 + threadIdx.x;
    if (e >= B_ * 260 * C_) return;
    int ci = e & 255, t = e >> 8, i = t % 260, b = t / 260;
    int py, px;
    if (i < 66)       { py = 0;       px = i; }
    else if (i < 132) { py = 65;      px = i - 66; }
    else if (i < 196) { py = i - 131; px = 0; }
    else              { py = i - 195; px = 65; }
    size_t a = (((size_t)b * P_ + py) * P_ + px) * C_ + ci;
    g_xt[a] = __float2half(0.f);
    g_ht[a] = __float2half(0.f);
}

__global__ void xprep_kernel(const float* __restrict__ x) {
    __shared__ float t[64][65];
    __shared__ float st[64];
    int tid = threadIdx.x, b = blockIdx.z, py = blockIdx.y, c0 = blockIdx.x << 6;
    if (tid < 64) st[tid] = g_style[0][b][c0 + tid];
    #pragma unroll 4
    for (int i = 0; i < 16; i++) {
        int ci = (i << 2) + (tid >> 6), px = tid & 63;
        t[ci][px] = x[(((size_t)b * C_ + c0 + ci) << 12) + (py << 6) + px];
    }
    __syncthreads();
    #pragma unroll 4
    for (int i = 0; i < 16; i++) {
        int px = (i << 2) + (tid >> 6), ci = tid & 63;
        float v = t[ci][px] * st[ci];
        size_t a = (((size_t)b * P_ + py + 1) * P_ + px + 1) * C_ + c0 + ci;
        g_xt[a] = __float2half(v);
    }
}

// ---------------- main conv: implicit GEMM, tap-reuse stages ----------------
// CTA: M=128 couts x N=128 px (2 image rows). Stage = cin16 chunk: B slab of
// 4 haloed rows x 66 px (8448B) + A 9 taps x 128 co (36864B). 16 stages,
// 4 slots, wait_group 2 (two full stages of L2-latency slack).
#define SLOT_B 8448
#define SLOT_A 36864
#define SLOT_BYTES (SLOT_B + SLOT_A)      // 45312
#define NSLOT 4
#define SMEM_CONV (NSLOT * SLOT_BYTES)    // 181248
#define NSTAGE 16

__device__ __forceinline__ uint32_t swz(int unit32, int half16) {
    // unit32: 32B-row index (px or co); half16: 0/16 byte offset (k-half)
    return (uint32_t)((unit32 * 32 + half16) ^ (((unit32 >> 2) & 1) << 4));
}

__global__ __launch_bounds__(256, 1)
void conv_hmma_kernel(const __half* __restrict__ xt, int wsel,
                      const float* __restrict__ nw,
                      const float* __restrict__ noise, int mode,
                      __half* __restrict__ o_h, float* __restrict__ outp) {
    extern __shared__ __align__(128) char smem_raw[];
    const uint32_t sb = smem_u32(smem_raw);

    const int tid = threadIdx.x;
    const int wid = tid >> 5, lane = tid & 31;
    const int warp_m = wid & 3, warp_n = wid >> 2;   // warp tile M=32, N=64 (one row)
    const int n0 = blockIdx.x << 7;                   // pixel tile base
    const int co0 = blockIdx.y << 7;
    const int b = blockIdx.z;
    const int r0 = blockIdx.x << 1;                   // padded-row base (img rows r0-1..r0+2)

    // ldmatrix lane mapping
    const int a_min  = (lane & 7) + ((lane >> 3) & 1) * 8;
    const int a_koff = (lane >> 4) << 4;
    const int b_nin  = ((lane >> 4) << 3) + (lane & 7);
    const int b_koff = ((lane >> 3) & 1) << 4;

    float acc[2][8][4];
    #pragma unroll
    for (int i = 0; i < 2; i++)
        #pragma unroll
        for (int j = 0; j < 8; j++)
            #pragma unroll
            for (int r = 0; r < 4; r++) acc[i][j][r] = 0.f;

    auto load_stage = [&](int s) {
        if (s < NSTAGE) {
            const uint32_t slot = sb + (s & 3) * SLOT_BYTES;
            const int cin0 = s << 4;
            // B slab: 4 rows x 66 px x 2 16B-units = 528 units
            #pragma unroll
            for (int i = tid; i < 528; i += 256) {
                int row = i / 132, rem = i - row * 132;
                int px = rem >> 1, u = rem & 1;
                cp16(slot + row * 2112 + swz(px, u << 4),
                     xt + ((((size_t)b * P_ + r0 + row) * P_ + px) << 8) + cin0 + (u << 3));
            }
            // A: 9 taps x 128 co x 2 units = 2304 units (contiguous gmem)
            const __half* wbase = &g_wf[wsel][0][s][co0][0];   // [tap][16][C][16] stride
            #pragma unroll
            for (int i = tid; i < 2304; i += 256) {
                int tap = i >> 8, rem = i & 255;
                int co = rem >> 1, u = rem & 1;
                cp16(slot + SLOT_B + tap * 4096 + swz(co, u << 4),
                     wbase + (size_t)tap * (16 * C_ * 16) + co * 16 + u * 8);
            }
        }
        cp_commit();
    };

    load_stage(0); load_stage(1); load_stage(2);

    #pragma unroll 1
    for (int s = 0; s < NSTAGE; s++) {
        cp_wait2();
        __syncthreads();
        load_stage(s + 3);
        const uint32_t slot = sb + (s & 3) * SLOT_BYTES;
        const uint32_t aslot = slot + SLOT_B;

        #pragma unroll
        for (int tap = 0; tap < 9; tap++) {
            const int dy = tap / 3, dx = tap - dy * 3;
            uint32_t a[2][4];
            #pragma unroll
            for (int f = 0; f < 2; f++) {
                int co_l = warp_m * 32 + f * 16 + a_min;
                ldmx4(a[f], aslot + tap * 4096 + swz(co_l, a_koff));
            }
            uint32_t bf[8][2];
            const uint32_t rowbase = slot + (warp_n + dy) * 2112;
            #pragma unroll
            for (int g = 0; g < 4; g++) {
                int ppx = g * 16 + b_nin + dx;
                uint32_t r[4];
                ldmx4(r, rowbase + swz(ppx, b_koff));
                bf[2 * g][0] = r[0]; bf[2 * g][1] = r[1];
                bf[2 * g + 1][0] = r[2]; bf[2 * g + 1][1] = r[3];
            }
            #pragma unroll
            for (int im = 0; im < 2; im++)
                #pragma unroll
                for (int in = 0; in < 8; in++)
                    mma16816(acc[im][in], a[im], bf[in]);
        }
    }
    __syncthreads();   // protect smem reuse in epilogue

    // ---------------- epilogue ----------------
    const int qm = lane >> 2;
    const int qn = (lane & 3) << 1;

    if (mode == 1) {
        #pragma unroll
        for (int im = 0; im < 2; im++) {
            #pragma unroll
            for (int rr = 0; rr < 2; rr++) {
                const int m = co0 + warp_m * 32 + im * 16 + qm + rr * 8;
                const float dm = g_demod[wsel][b][m];
                const float nwv = nw[m];
                float* ob = outp + (((size_t)b << 8) + m) * 4096;
                #pragma unroll
                for (int in = 0; in < 8; in++) {
                    const int n = n0 + warp_n * 64 + in * 8 + qn;
                    float v0 = acc[im][in][rr * 2 + 0] * dm + nwv * noise[((size_t)b << 12) + n];
                    float v1 = acc[im][in][rr * 2 + 1] * dm + nwv * noise[((size_t)b << 12) + n + 1];
                    v0 = v0 > 0.f ? v0 : 0.2f * v0;
                    v1 = v1 > 0.f ? v1 : 0.2f * v1;
                    *reinterpret_cast<float2*>(ob + n) = make_float2(v0, v1);
                }
            }
        }
    } else {
        __half* hs = reinterpret_cast<__half*>(smem_raw);   // [128 n][stride 136]
        #pragma unroll
        for (int im = 0; im < 2; im++) {
            #pragma unroll
            for (int rr = 0; rr < 2; rr++) {
                const int ml = warp_m * 32 + im * 16 + qm + rr * 8;
                const int m = co0 + ml;
                const float dm = g_demod[wsel][b][m];
                const float nwv = nw[m];
                const float sty = g_style[1][b][m];
                #pragma unroll
                for (int in = 0; in < 8; in++) {
                    const int nl = warp_n * 64 + in * 8 + qn;
                    const int n = n0 + nl;
                    float v0 = acc[im][in][rr * 2 + 0] * dm + nwv * noise[((size_t)b << 12) + n];
                    float v1 = acc[im][in][rr * 2 + 1] * dm + nwv * noise[((size_t)b << 12) + n + 1];
                    v0 = (v0 > 0.f ? v0 : 0.2f * v0) * sty;
                    v1 = (v1 > 0.f ? v1 : 0.2f * v1) * sty;
                    hs[nl * 136 + ml] = __float2half(v0);
                    hs[(nl + 1) * 136 + ml] = __float2half(v1);
                }
            }
        }
        __syncthreads();
        const int nl = tid >> 1, half = tid & 1;
        const int pix = n0 + nl;
        const int py = (pix >> 6) + 1, px = (pix & 63) + 1;
        const uint4* src = reinterpret_cast<const uint4*>(hs + nl * 136 + half * 64);
        uint4* dst = reinterpret_cast<uint4*>(
            o_h + ((((size_t)b * P_ + py) * P_ + px) << 8) + co0 + half * 64);
        #pragma unroll
        for (int i = 0; i < 8; i++) dst[i] = src[i];
    }
}

// ---------------- launcher ----------------
extern "C" void kernel_launch(void* const* d_in, const int* in_sizes, int n_in,
                              void* d_out, int out_size) {
    const float* x       = (const float*)d_in[0];
    const float* w1      = (const float*)d_in[1];
    const float* w2      = (const float*)d_in[2];
    const float* noise1  = (const float*)d_in[3];
    const float* noise2  = (const float*)d_in[4];
    const float* s1_w    = (const float*)d_in[5];
    const float* s1_b    = (const float*)d_in[6];
    const float* conv1_w = (const float*)d_in[7];
    const float* nw1     = (const float*)d_in[8];
    const float* s2_w    = (const float*)d_in[9];
    const float* s2_b    = (const float*)d_in[10];
    const float* conv2_w = (const float*)d_in[11];
    const float* nw2     = (const float*)d_in[12];
    float* out = (float*)d_out;

    __half *p_xt, *p_ht;
    cudaGetSymbolAddress((void**)&p_xt, g_xt);
    cudaGetSymbolAddress((void**)&p_ht, g_ht);

    cudaFuncSetAttribute(conv_hmma_kernel,
                         cudaFuncAttributeMaxDynamicSharedMemorySize, SMEM_CONV);

    wprep_kernel<<<(2 * C_ * C_ + 255) / 256, 256>>>(conv1_w, conv2_w);
    style_kernel<<<1024, 256>>>(w1, w2, s1_w, s1_b, s2_w, s2_b);
    halo_kernel<<<(B_ * 260 * C_ + 255) / 256, 256>>>();
    xprep_kernel<<<dim3(4, 64, 16), 256>>>(x);
    demod_kernel<<<1024, 256>>>();

    dim3 grid(32, 2, 16);
    conv_hmma_kernel<<<grid, 256, SMEM_CONV>>>(p_xt, 0, nw1, noise1, 0, p_ht, nullptr);
    conv_hmma_kernel<<<grid, 256, SMEM_CONV>>>(p_ht, 1, nw2, noise2, 1, nullptr, out);
}

// round 11
// speedup vs baseline: 11.9173x; 1.1859x over previous
#include <cuda_runtime.h>
#include <cuda_fp16.h>
#include <cstdint>

#define B_ 16
#define C_ 256
#define S_ 512
#define P_ 66
#define STYLE_SCALE 0.03125f
#define EPS_ 1e-8f
#define XT_ELEMS ((size_t)B_ * P_ * P_ * C_)

// ---------------- device scratch ----------------
__device__ __half g_xt[XT_ELEMS];            // style1-scaled x, NHWC padded, fp16
__device__ __half g_ht[XT_ELEMS];            // style2-scaled h, NHWC padded, fp16
__device__ __half g_wf[2][9][16][C_][16];    // weights fp16 [conv][tap][cin16][cout][cin&15]
__device__ float  g_wsq[2][C_][C_];
__device__ float  g_style[2][B_][C_];
__device__ float  g_demod[2][B_][C_];

// ---------------- PTX helpers ----------------
__device__ __forceinline__ uint32_t smem_u32(const void* p) {
    uint32_t a;
    asm("{ .reg .u64 t; cvta.to.shared.u64 t, %1; cvt.u32.u64 %0, t; }" : "=r"(a) : "l"(p));
    return a;
}
__device__ __forceinline__ void cp16(uint32_t s, const void* g) {
    asm volatile("cp.async.cg.shared.global [%0], [%1], 16;" :: "r"(s), "l"(g));
}
__device__ __forceinline__ void cp_commit() { asm volatile("cp.async.commit_group;" ::: "memory"); }
__device__ __forceinline__ void cp_wait1()  { asm volatile("cp.async.wait_group 1;" ::: "memory"); }
__device__ __forceinline__ void ldmx4(uint32_t* r, uint32_t a) {
    asm volatile("ldmatrix.sync.aligned.m8n8.x4.shared.b16 {%0,%1,%2,%3}, [%4];"
                 : "=r"(r[0]), "=r"(r[1]), "=r"(r[2]), "=r"(r[3]) : "r"(a));
}
__device__ __forceinline__ void mma16816(float* d, const uint32_t* a, const uint32_t* b) {
    asm volatile(
        "mma.sync.aligned.m16n8k16.row.col.f32.f16.f16.f32 "
        "{%0,%1,%2,%3}, {%4,%5,%6,%7}, {%8,%9}, {%0,%1,%2,%3};"
        : "+f"(d[0]), "+f"(d[1]), "+f"(d[2]), "+f"(d[3])
        : "r"(a[0]), "r"(a[1]), "r"(a[2]), "r"(a[3]), "r"(b[0]), "r"(b[1]));
}

// ---------------- prep kernels ----------------
__global__ void wprep_kernel(const float* __restrict__ w1, const float* __restrict__ w2) {
    int idx = blockIdx.x * 256 + threadIdx.x;
    if (idx >= 2 * C_ * C_) return;
    int cv = idx >> 16, co = (idx >> 8) & 255, ci = idx & 255;
    const float* w = cv ? w2 : w1;
    float sq = 0.f;
    #pragma unroll
    for (int k = 0; k < 9; k++) {
        float v = w[(co * C_ + ci) * 9 + k];
        sq += v * v;
        g_wf[cv][k][ci >> 4][co][ci & 15] = __float2half(v);
    }
    g_wsq[cv][co][ci] = sq;
}

__global__ void style_kernel(const float* __restrict__ w1v, const float* __restrict__ w2v,
                             const float* __restrict__ s1w, const float* __restrict__ s1b,
                             const float* __restrict__ s2w, const float* __restrict__ s2b) {
    int gw = blockIdx.x * 8 + (threadIdx.x >> 5), lane = threadIdx.x & 31;
    int cv = gw >> 12, b = (gw >> 8) & 15, c = gw & 255;
    const float* wv = (cv ? w2v : w1v) + b * S_;
    const float* sr = (cv ? s2w : s1w) + c * S_;
    float sum = 0.f;
    #pragma unroll 4
    for (int s = lane; s < S_; s += 32) sum += wv[s] * sr[s];
    #pragma unroll
    for (int o = 16; o > 0; o >>= 1) sum += __shfl_down_sync(0xffffffffu, sum, o);
    if (lane == 0) g_style[cv][b][c] = sum * STYLE_SCALE + (cv ? s2b : s1b)[c];
}

__global__ void demod_kernel() {
    int gw = blockIdx.x * 8 + (threadIdx.x >> 5), lane = threadIdx.x & 31;
    int cv = gw >> 12, b = (gw >> 8) & 15, co = gw & 255;
    float sum = 0.f;
    #pragma unroll 4
    for (int ci = lane; ci < C_; ci += 32) {
        float s = g_style[cv][b][ci];
        sum += s * s * g_wsq[cv][co][ci];
    }
    #pragma unroll
    for (int o = 16; o > 0; o >>= 1) sum += __shfl_down_sync(0xffffffffu, sum, o);
    if (lane == 0) g_demod[cv][b][co] = rsqrtf(sum + EPS_);
}

__global__ void halo_kernel() {
    int e = blockIdx.x * 256 + threadIdx.x;
    if (e >= B_ * 260 * C_) return;
    int ci = e & 255, t = e >> 8, i = t % 260, b = t / 260;
    int py, px;
    if (i < 66)       { py = 0;       px = i; }
    else if (i < 132) { py = 65;      px = i - 66; }
    else if (i < 196) { py = i - 131; px = 0; }
    else              { py = i - 195; px = 65; }
    size_t a = (((size_t)b * P_ + py) * P_ + px) * C_ + ci;
    g_xt[a] = __float2half(0.f);
    g_ht[a] = __float2half(0.f);
}

__global__ void xprep_kernel(const float* __restrict__ x) {
    __shared__ float t[64][65];
    __shared__ float st[64];
    int tid = threadIdx.x, b = blockIdx.z, py = blockIdx.y, c0 = blockIdx.x << 6;
    if (tid < 64) st[tid] = g_style[0][b][c0 + tid];
    #pragma unroll 4
    for (int i = 0; i < 16; i++) {
        int ci = (i << 2) + (tid >> 6), px = tid & 63;
        t[ci][px] = x[(((size_t)b * C_ + c0 + ci) << 12) + (py << 6) + px];
    }
    __syncthreads();
    #pragma unroll 4
    for (int i = 0; i < 16; i++) {
        int px = (i << 2) + (tid >> 6), ci = tid & 63;
        float v = t[ci][px] * st[ci];
        size_t a = (((size_t)b * P_ + py + 1) * P_ + px + 1) * C_ + c0 + ci;
        g_xt[a] = __float2half(v);
    }
}

// ---------------- main conv: implicit GEMM, tap-reuse stages, occ 2 ----------------
// CTA: M=128 couts x N=128 px (2 image rows). Stage = cin16 chunk: B slab of
// 4 haloed rows x 66 px (8448B) + A 9 taps x 128 co (36864B). 16 stages,
// 2 slots (double buffer, wait_group 1), 2 CTAs/SM for latency cover.
#define SLOT_B 8448
#define SLOT_A 36864
#define SLOT_BYTES (SLOT_B + SLOT_A)      // 45312
#define NSLOT 2
#define SMEM_CONV (NSLOT * SLOT_BYTES)    // 90624
#define NSTAGE 16

__device__ __forceinline__ uint32_t swz(int unit32, int half16) {
    // unit32: 32B-row index (px or co); half16: 0/16 byte offset (k-half)
    return (uint32_t)((unit32 * 32 + half16) ^ (((unit32 >> 2) & 1) << 4));
}

__global__ __launch_bounds__(256, 2)
void conv_hmma_kernel(const __half* __restrict__ xt, int wsel,
                      const float* __restrict__ nw,
                      const float* __restrict__ noise, int mode,
                      __half* __restrict__ o_h, float* __restrict__ outp) {
    extern __shared__ __align__(128) char smem_raw[];
    const uint32_t sb = smem_u32(smem_raw);

    const int tid = threadIdx.x;
    const int wid = tid >> 5, lane = tid & 31;
    const int warp_m = wid & 3, warp_n = wid >> 2;   // warp tile M=32, N=64 (one row)
    const int n0 = blockIdx.x << 7;                   // pixel tile base
    const int co0 = blockIdx.y << 7;
    const int b = blockIdx.z;
    const int r0 = blockIdx.x << 1;                   // padded-row base

    // ldmatrix lane mapping
    const int a_min  = (lane & 7) + ((lane >> 3) & 1) * 8;
    const int a_koff = (lane >> 4) << 4;
    const int b_nin  = ((lane >> 4) << 3) + (lane & 7);
    const int b_koff = ((lane >> 3) & 1) << 4;

    float acc[2][8][4];
    #pragma unroll
    for (int i = 0; i < 2; i++)
        #pragma unroll
        for (int j = 0; j < 8; j++)
            #pragma unroll
            for (int r = 0; r < 4; r++) acc[i][j][r] = 0.f;

    auto load_stage = [&](int s) {
        if (s < NSTAGE) {
            const uint32_t slot = sb + (s & 1) * SLOT_BYTES;
            const int cin0 = s << 4;
            // B slab: 4 rows x 66 px x 2 16B-units = 528 units
            #pragma unroll
            for (int i = tid; i < 528; i += 256) {
                int row = i / 132, rem = i - row * 132;
                int px = rem >> 1, u = rem & 1;
                cp16(slot + row * 2112 + swz(px, u << 4),
                     xt + ((((size_t)b * P_ + r0 + row) * P_ + px) << 8) + cin0 + (u << 3));
            }
            // A: 9 taps x 128 co x 2 units = 2304 units (contiguous gmem)
            const __half* wbase = &g_wf[wsel][0][s][co0][0];
            #pragma unroll
            for (int i = tid; i < 2304; i += 256) {
                int tap = i >> 8, rem = i & 255;
                int co = rem >> 1, u = rem & 1;
                cp16(slot + SLOT_B + tap * 4096 + swz(co, u << 4),
                     wbase + (size_t)tap * (16 * C_ * 16) + co * 16 + u * 8);
            }
        }
        cp_commit();
    };

    load_stage(0);

    #pragma unroll 1
    for (int s = 0; s < NSTAGE; s++) {
        load_stage(s + 1);      // into slot (s+1)&1 — freed by barrier at end of s-1
        cp_wait1();             // stage s resident, stage s+1 in flight
        __syncthreads();
        const uint32_t slot = sb + (s & 1) * SLOT_BYTES;
        const uint32_t aslot = slot + SLOT_B;

        #pragma unroll
        for (int tap = 0; tap < 9; tap++) {
            const int dy = tap / 3, dx = tap - dy * 3;
            uint32_t a[2][4];
            #pragma unroll
            for (int f = 0; f < 2; f++) {
                int co_l = warp_m * 32 + f * 16 + a_min;
                ldmx4(a[f], aslot + tap * 4096 + swz(co_l, a_koff));
            }
            uint32_t bf[8][2];
            const uint32_t rowbase = slot + (warp_n + dy) * 2112;
            #pragma unroll
            for (int g = 0; g < 4; g++) {
                int ppx = g * 16 + b_nin + dx;
                uint32_t r[4];
                ldmx4(r, rowbase + swz(ppx, b_koff));
                bf[2 * g][0] = r[0]; bf[2 * g][1] = r[1];
                bf[2 * g + 1][0] = r[2]; bf[2 * g + 1][1] = r[3];
            }
            #pragma unroll
            for (int im = 0; im < 2; im++)
                #pragma unroll
                for (int in = 0; in < 8; in++)
                    mma16816(acc[im][in], a[im], bf[in]);
        }
        __syncthreads();        // slot (s&1) now reusable by load(s+2)
    }

    // ---------------- epilogue ----------------
    const int qm = lane >> 2;
    const int qn = (lane & 3) << 1;

    if (mode == 1) {
        #pragma unroll
        for (int im = 0; im < 2; im++) {
            #pragma unroll
            for (int rr = 0; rr < 2; rr++) {
                const int m = co0 + warp_m * 32 + im * 16 + qm + rr * 8;
                const float dm = g_demod[wsel][b][m];
                const float nwv = nw[m];
                float* ob = outp + (((size_t)b << 8) + m) * 4096;
                #pragma unroll
                for (int in = 0; in < 8; in++) {
                    const int n = n0 + warp_n * 64 + in * 8 + qn;
                    float v0 = acc[im][in][rr * 2 + 0] * dm + nwv * noise[((size_t)b << 12) + n];
                    float v1 = acc[im][in][rr * 2 + 1] * dm + nwv * noise[((size_t)b << 12) + n + 1];
                    v0 = v0 > 0.f ? v0 : 0.2f * v0;
                    v1 = v1 > 0.f ? v1 : 0.2f * v1;
                    *reinterpret_cast<float2*>(ob + n) = make_float2(v0, v1);
                }
            }
        }
    } else {
        __half* hs = reinterpret_cast<__half*>(smem_raw);   // [128 n][stride 136]
        #pragma unroll
        for (int im = 0; im < 2; im++) {
            #pragma unroll
            for (int rr = 0; rr < 2; rr++) {
                const int ml = warp_m * 32 + im * 16 + qm + rr * 8;
                const int m = co0 + ml;
                const float dm = g_demod[wsel][b][m];
                const float nwv = nw[m];
                const float sty = g_style[1][b][m];
                #pragma unroll
                for (int in = 0; in < 8; in++) {
                    const int nl = warp_n * 64 + in * 8 + qn;
                    const int n = n0 + nl;
                    float v0 = acc[im][in][rr * 2 + 0] * dm + nwv * noise[((size_t)b << 12) + n];
                    float v1 = acc[im][in][rr * 2 + 1] * dm + nwv * noise[((size_t)b << 12) + n + 1];
                    v0 = (v0 > 0.f ? v0 : 0.2f * v0) * sty;
                    v1 = (v1 > 0.f ? v1 : 0.2f * v1) * sty;
                    hs[nl * 136 + ml] = __float2half(v0);
                    hs[(nl + 1) * 136 + ml] = __float2half(v1);
                }
            }
        }
        __syncthreads();
        const int nl = tid >> 1, half = tid & 1;
        const int pix = n0 + nl;
        const int py = (pix >> 6) + 1, px = (pix & 63) + 1;
        const uint4* src = reinterpret_cast<const uint4*>(hs + nl * 136 + half * 64);
        uint4* dst = reinterpret_cast<uint4*>(
            o_h + ((((size_t)b * P_ + py) * P_ + px) << 8) + co0 + half * 64);
        #pragma unroll
        for (int i = 0; i < 8; i++) dst[i] = src[i];
    }
}

// ---------------- launcher ----------------
extern "C" void kernel_launch(void* const* d_in, const int* in_sizes, int n_in,
                              void* d_out, int out_size) {
    const float* x       = (const float*)d_in[0];
    const float* w1      = (const float*)d_in[1];
    const float* w2      = (const float*)d_in[2];
    const float* noise1  = (const float*)d_in[3];
    const float* noise2  = (const float*)d_in[4];
    const float* s1_w    = (const float*)d_in[5];
    const float* s1_b    = (const float*)d_in[6];
    const float* conv1_w = (const float*)d_in[7];
    const float* nw1     = (const float*)d_in[8];
    const float* s2_w    = (const float*)d_in[9];
    const float* s2_b    = (const float*)d_in[10];
    const float* conv2_w = (const float*)d_in[11];
    const float* nw2     = (const float*)d_in[12];
    float* out = (float*)d_out;

    __half *p_xt, *p_ht;
    cudaGetSymbolAddress((void**)&p_xt, g_xt);
    cudaGetSymbolAddress((void**)&p_ht, g_ht);

    cudaFuncSetAttribute(conv_hmma_kernel,
                         cudaFuncAttributeMaxDynamicSharedMemorySize, SMEM_CONV);

    wprep_kernel<<<(2 * C_ * C_ + 255) / 256, 256>>>(conv1_w, conv2_w);
    style_kernel<<<1024, 256>>>(w1, w2, s1_w, s1_b, s2_w, s2_b);
    halo_kernel<<<(B_ * 260 * C_ + 255) / 256, 256>>>();
    xprep_kernel<<<dim3(4, 64, 16), 256>>>(x);
    demod_kernel<<<1024, 256>>>();

    dim3 grid(32, 2, 16);
    conv_hmma_kernel<<<grid, 256, SMEM_CONV>>>(p_xt, 0, nw1, noise1, 0, p_ht, nullptr);
    conv_hmma_kernel<<<grid, 256, SMEM_CONV>>>(p_ht, 1, nw2, noise2, 1, nullptr, out);
}

// round 13
// speedup vs baseline: 12.1664x; 1.0209x over previous
#include <cuda_runtime.h>
#include <cuda_fp16.h>
#include <cstdint>

#define B_ 16
#define C_ 256
#define S_ 512
#define P_ 66
#define STYLE_SCALE 0.03125f
#define EPS_ 1e-8f
#define XT_ELEMS ((size_t)B_ * P_ * P_ * C_)

// ---------------- device scratch ----------------
__device__ __half g_xt[XT_ELEMS];            // style1-scaled x, NHWC padded, fp16
__device__ __half g_ht[XT_ELEMS];            // style2-scaled h, NHWC padded, fp16
__device__ __half g_wf[2][9][16][C_][16];    // weights fp16 [conv][tap][cin16][cout][cin&15]
__device__ float  g_wsq[2][C_][C_];
__device__ float  g_style[2][B_][C_];
__device__ float  g_demod[2][B_][C_];

// ---------------- PTX helpers ----------------
__device__ __forceinline__ uint32_t smem_u32(const void* p) {
    uint32_t a;
    asm("{ .reg .u64 t; cvta.to.shared.u64 t, %1; cvt.u32.u64 %0, t; }" : "=r"(a) : "l"(p));
    return a;
}
__device__ __forceinline__ void cp16(uint32_t s, const void* g) {
    asm volatile("cp.async.cg.shared.global [%0], [%1], 16;" :: "r"(s), "l"(g));
}
__device__ __forceinline__ void cp_commit() { asm volatile("cp.async.commit_group;" ::: "memory"); }
__device__ __forceinline__ void cp_wait1()  { asm volatile("cp.async.wait_group 1;" ::: "memory"); }
__device__ __forceinline__ void ldmx4(uint32_t* r, uint32_t a) {
    asm volatile("ldmatrix.sync.aligned.m8n8.x4.shared.b16 {%0,%1,%2,%3}, [%4];"
                 : "=r"(r[0]), "=r"(r[1]), "=r"(r[2]), "=r"(r[3]) : "r"(a));
}
__device__ __forceinline__ void mma16816(float* d, const uint32_t* a, const uint32_t* b) {
    asm volatile(
        "mma.sync.aligned.m16n8k16.row.col.f32.f16.f16.f32 "
        "{%0,%1,%2,%3}, {%4,%5,%6,%7}, {%8,%9}, {%0,%1,%2,%3};"
        : "+f"(d[0]), "+f"(d[1]), "+f"(d[2]), "+f"(d[3])
        : "r"(a[0]), "r"(a[1]), "r"(a[2]), "r"(a[3]), "r"(b[0]), "r"(b[1]));
}

// ================= prep1: wprep (blocks 0..511) + style (blocks 512..1535) ==========
#define PREP1_WBLOCKS 512     // 2*C*C / 256
#define PREP1_BLOCKS  1536
__global__ void prep1_kernel(const float* __restrict__ w1, const float* __restrict__ w2,
                             const float* __restrict__ w1v, const float* __restrict__ w2v,
                             const float* __restrict__ s1w, const float* __restrict__ s1b,
                             const float* __restrict__ s2w, const float* __restrict__ s2b) {
    if (blockIdx.x < PREP1_WBLOCKS) {
        int idx = blockIdx.x * 256 + threadIdx.x;     // 2*C*C
        int cv = idx >> 16, co = (idx >> 8) & 255, ci = idx & 255;
        const float* w = cv ? w2 : w1;
        float sq = 0.f;
        #pragma unroll
        for (int k = 0; k < 9; k++) {
            float v = w[(co * C_ + ci) * 9 + k];
            sq += v * v;
            g_wf[cv][k][ci >> 4][co][ci & 15] = __float2half(v);
        }
        g_wsq[cv][co][ci] = sq;
    } else {
        int gw = (blockIdx.x - PREP1_WBLOCKS) * 8 + (threadIdx.x >> 5);   // 2*B*C warps
        int lane = threadIdx.x & 31;
        int cv = gw >> 12, b = (gw >> 8) & 15, c = gw & 255;
        const float* wv = (cv ? w2v : w1v) + b * S_;
        const float* sr = (cv ? s2w : s1w) + c * S_;
        float sum = 0.f;
        #pragma unroll 4
        for (int s = lane; s < S_; s += 32) sum += wv[s] * sr[s];
        #pragma unroll
        for (int o = 16; o > 0; o >>= 1) sum += __shfl_down_sync(0xffffffffu, sum, o);
        if (lane == 0) g_style[cv][b][c] = sum * STYLE_SCALE + (cv ? s2b : s1b)[c];
    }
}

// ========= prep2: xprep (0..4095) + halo (4096..8255) + demod (8256..9279) ==========
#define PREP2_XBLOCKS 4096
#define PREP2_HBLOCKS 4160    // ceil(B*260*C / 256)
#define PREP2_BLOCKS  (PREP2_XBLOCKS + PREP2_HBLOCKS + 1024)
__global__ void prep2_kernel(const float* __restrict__ x) {
    __shared__ float t[64][65];
    __shared__ float st[64];
    const int tid = threadIdx.x;
    if (blockIdx.x < PREP2_XBLOCKS) {
        // ---- xprep: x (NCHW fp32) -> style1-scaled padded NHWC fp16 ----
        int blk = blockIdx.x;
        int c0 = (blk & 3) << 6, py = (blk >> 2) & 63, b = blk >> 8;
        if (tid < 64) st[tid] = g_style[0][b][c0 + tid];
        #pragma unroll 4
        for (int i = 0; i < 16; i++) {
            int ci = (i << 2) + (tid >> 6), px = tid & 63;
            t[ci][px] = x[(((size_t)b * C_ + c0 + ci) << 12) + (py << 6) + px];
        }
        __syncthreads();
        #pragma unroll 4
        for (int i = 0; i < 16; i++) {
            int px = (i << 2) + (tid >> 6), ci = tid & 63;
            float v = t[ci][px] * st[ci];
            size_t a = (((size_t)b * P_ + py + 1) * P_ + px + 1) * C_ + c0 + ci;
            g_xt[a] = __float2half(v);
        }
    } else if (blockIdx.x < PREP2_XBLOCKS + PREP2_HBLOCKS) {
        // ---- halo ring zeroing for both padded buffers ----
        int e = (blockIdx.x - PREP2_XBLOCKS) * 256 + tid;
        if (e >= B_ * 260 * C_) return;
        int ci = e & 255, tt = e >> 8, i = tt % 260, b = tt / 260;
        int py, px;
        if (i < 66)       { py = 0;       px = i; }
        else if (i < 132) { py = 65;      px = i - 66; }
        else if (i < 196) { py = i - 131; px = 0; }
        else              { py = i - 195; px = 65; }
        size_t a = (((size_t)b * P_ + py) * P_ + px) * C_ + ci;
        g_xt[a] = __float2half(0.f);
        g_ht[a] = __float2half(0.f);
    } else {
        // ---- demod ----
        int gw = (blockIdx.x - PREP2_XBLOCKS - PREP2_HBLOCKS) * 8 + (tid >> 5);
        int lane = tid & 31;
        int cv = gw >> 12, b = (gw >> 8) & 15, co = gw & 255;
        float sum = 0.f;
        #pragma unroll 4
        for (int ci = lane; ci < C_; ci += 32) {
            float s = g_style[cv][b][ci];
            sum += s * s * g_wsq[cv][co][ci];
        }
        #pragma unroll
        for (int o = 16; o > 0; o >>= 1) sum += __shfl_down_sync(0xffffffffu, sum, o);
        if (lane == 0) g_demod[cv][b][co] = rsqrtf(sum + EPS_);
    }
}

// ---------------- main conv: implicit GEMM, tap-reuse stages, occ 2 ----------------
// CTA: M=128 couts x N=128 px (2 image rows). Stage = cin16 chunk: B slab of
// 4 haloed rows x 66 px (8448B) + A 9 taps x 128 co (36864B). 16 stages,
// 2 slots (double buffer, wait_group 1), 2 CTAs/SM for latency cover.
#define SLOT_B 8448
#define SLOT_A 36864
#define SLOT_BYTES (SLOT_B + SLOT_A)      // 45312
#define NSLOT 2
#define SMEM_CONV (NSLOT * SLOT_BYTES)    // 90624
#define NSTAGE 16

__device__ __forceinline__ uint32_t swz(int unit32, int half16) {
    return (uint32_t)((unit32 * 32 + half16) ^ (((unit32 >> 2) & 1) << 4));
}

__global__ __launch_bounds__(256, 2)
void conv_hmma_kernel(const __half* __restrict__ xt, int wsel,
                      const float* __restrict__ nw,
                      const float* __restrict__ noise, int mode,
                      __half* __restrict__ o_h, float* __restrict__ outp) {
    extern __shared__ __align__(128) char smem_raw[];
    const uint32_t sb = smem_u32(smem_raw);

    const int tid = threadIdx.x;
    const int wid = tid >> 5, lane = tid & 31;
    const int warp_m = wid & 3, warp_n = wid >> 2;
    const int n0 = blockIdx.x << 7;
    const int co0 = blockIdx.y << 7;
    const int b = blockIdx.z;
    const int r0 = blockIdx.x << 1;

    const int a_min  = (lane & 7) + ((lane >> 3) & 1) * 8;
    const int a_koff = (lane >> 4) << 4;
    const int b_nin  = ((lane >> 4) << 3) + (lane & 7);
    const int b_koff = ((lane >> 3) & 1) << 4;

    float acc[2][8][4];
    #pragma unroll
    for (int i = 0; i < 2; i++)
        #pragma unroll
        for (int j = 0; j < 8; j++)
            #pragma unroll
            for (int r = 0; r < 4; r++) acc[i][j][r] = 0.f;

    auto load_stage = [&](int s) {
        if (s < NSTAGE) {
            const uint32_t slot = sb + (s & 1) * SLOT_BYTES;
            const int cin0 = s << 4;
            #pragma unroll
            for (int i = tid; i < 528; i += 256) {
                int row = i / 132, rem = i - row * 132;
                int px = rem >> 1, u = rem & 1;
                cp16(slot + row * 2112 + swz(px, u << 4),
                     xt + ((((size_t)b * P_ + r0 + row) * P_ + px) << 8) + cin0 + (u << 3));
            }
            const __half* wbase = &g_wf[wsel][0][s][co0][0];
            #pragma unroll
            for (int i = tid; i < 2304; i += 256) {
                int tap = i >> 8, rem = i & 255;
                int co = rem >> 1, u = rem & 1;
                cp16(slot + SLOT_B + tap * 4096 + swz(co, u << 4),
                     wbase + (size_t)tap * (16 * C_ * 16) + co * 16 + u * 8);
            }
        }
        cp_commit();
    };

    load_stage(0);

    #pragma unroll 1
    for (int s = 0; s < NSTAGE; s++) {
        load_stage(s + 1);
        cp_wait1();
        __syncthreads();
        const uint32_t slot = sb + (s & 1) * SLOT_BYTES;
        const uint32_t aslot = slot + SLOT_B;

        #pragma unroll
        for (int tap = 0; tap < 9; tap++) {
            const int dy = tap / 3, dx = tap - dy * 3;
            uint32_t a[2][4];
            #pragma unroll
            for (int f = 0; f < 2; f++) {
                int co_l = warp_m * 32 + f * 16 + a_min;
                ldmx4(a[f], aslot + tap * 4096 + swz(co_l, a_koff));
            }
            uint32_t bf[8][2];
            const uint32_t rowbase = slot + (warp_n + dy) * 2112;
            #pragma unroll
            for (int g = 0; g < 4; g++) {
                int ppx = g * 16 + b_nin + dx;
                uint32_t r[4];
                ldmx4(r, rowbase + swz(ppx, b_koff));
                bf[2 * g][0] = r[0]; bf[2 * g][1] = r[1];
                bf[2 * g + 1][0] = r[2]; bf[2 * g + 1][1] = r[3];
            }
            #pragma unroll
            for (int im = 0; im < 2; im++)
                #pragma unroll
                for (int in = 0; in < 8; in++)
                    mma16816(acc[im][in], a[im], bf[in]);
        }
        __syncthreads();
    }

    // ---------------- epilogue ----------------
    const int qm = lane >> 2;
    const int qn = (lane & 3) << 1;

    if (mode == 1) {
        #pragma unroll
        for (int im = 0; im < 2; im++) {
            #pragma unroll
            for (int rr = 0; rr < 2; rr++) {
                const int m = co0 + warp_m * 32 + im * 16 + qm + rr * 8;
                const float dm = g_demod[wsel][b][m];
                const float nwv = nw[m];
                float* ob = outp + (((size_t)b << 8) + m) * 4096;
                #pragma unroll
                for (int in = 0; in < 8; in++) {
                    const int n = n0 + warp_n * 64 + in * 8 + qn;
                    float v0 = acc[im][in][rr * 2 + 0] * dm + nwv * noise[((size_t)b << 12) + n];
                    float v1 = acc[im][in][rr * 2 + 1] * dm + nwv * noise[((size_t)b << 12) + n + 1];
                    v0 = v0 > 0.f ? v0 : 0.2f * v0;
                    v1 = v1 > 0.f ? v1 : 0.2f * v1;
                    *reinterpret_cast<float2*>(ob + n) = make_float2(v0, v1);
                }
            }
        }
    } else {
        __half* hs = reinterpret_cast<__half*>(smem_raw);   // [128 n][stride 136]
        #pragma unroll
        for (int im = 0; im < 2; im++) {
            #pragma unroll
            for (int rr = 0; rr < 2; rr++) {
                const int ml = warp_m * 32 + im * 16 + qm + rr * 8;
                const int m = co0 + ml;
                const float dm = g_demod[wsel][b][m];
                const float nwv = nw[m];
                const float sty = g_style[1][b][m];
                #pragma unroll
                for (int in = 0; in < 8; in++) {
                    const int nl = warp_n * 64 + in * 8 + qn;
                    const int n = n0 + nl;
                    float v0 = acc[im][in][rr * 2 + 0] * dm + nwv * noise[((size_t)b << 12) + n];
                    float v1 = acc[im][in][rr * 2 + 1] * dm + nwv * noise[((size_t)b << 12) + n + 1];
                    v0 = (v0 > 0.f ? v0 : 0.2f * v0) * sty;
                    v1 = (v1 > 0.f ? v1 : 0.2f * v1) * sty;
                    hs[nl * 136 + ml] = __float2half(v0);
                    hs[(nl + 1) * 136 + ml] = __float2half(v1);
                }
            }
        }
        __syncthreads();
        const int nl = tid >> 1, half = tid & 1;
        const int pix = n0 + nl;
        const int py = (pix >> 6) + 1, px = (pix & 63) + 1;
        const uint4* src = reinterpret_cast<const uint4*>(hs + nl * 136 + half * 64);
        uint4* dst = reinterpret_cast<uint4*>(
            o_h + ((((size_t)b * P_ + py) * P_ + px) << 8) + co0 + half * 64);
        #pragma unroll
        for (int i = 0; i < 8; i++) dst[i] = src[i];
    }
}

// ---------------- launcher ----------------
extern "C" void kernel_launch(void* const* d_in, const int* in_sizes, int n_in,
                              void* d_out, int out_size) {
    const float* x       = (const float*)d_in[0];
    const float* w1      = (const float*)d_in[1];
    const float* w2      = (const float*)d_in[2];
    const float* noise1  = (const float*)d_in[3];
    const float* noise2  = (const float*)d_in[4];
    const float* s1_w    = (const float*)d_in[5];
    const float* s1_b    = (const float*)d_in[6];
    const float* conv1_w = (const float*)d_in[7];
    const float* nw1     = (const float*)d_in[8];
    const float* s2_w    = (const float*)d_in[9];
    const float* s2_b    = (const float*)d_in[10];
    const float* conv2_w = (const float*)d_in[11];
    const float* nw2     = (const float*)d_in[12];
    float* out = (float*)d_out;

    __half *p_xt, *p_ht;
    cudaGetSymbolAddress((void**)&p_xt, g_xt);
    cudaGetSymbolAddress((void**)&p_ht, g_ht);

    cudaFuncSetAttribute(conv_hmma_kernel,
                         cudaFuncAttributeMaxDynamicSharedMemorySize, SMEM_CONV);

    prep1_kernel<<<PREP1_BLOCKS, 256>>>(conv1_w, conv2_w, w1, w2,
                                        s1_w, s1_b, s2_w, s2_b);
    prep2_kernel<<<PREP2_BLOCKS, 256>>>(x);

    dim3 grid(32, 2, 16);
    conv_hmma_kernel<<<grid, 256, SMEM_CONV>>>(p_xt, 0, nw1, noise1, 0, p_ht, nullptr);
    conv_hmma_kernel<<<grid, 256, SMEM_CONV>>>(p_ht, 1, nw2, noise2, 1, nullptr, out);
}

// round 15
// speedup vs baseline: 12.2542x; 1.0072x over previous
#include <cuda_runtime.h>
#include <cuda_fp16.h>
#include <cstdint>

#define B_ 16
#define C_ 256
#define S_ 512
#define P_ 66
#define STYLE_SCALE 0.03125f
#define EPS_ 1e-8f
#define XT_ELEMS ((size_t)B_ * P_ * P_ * C_)

// ---------------- device scratch ----------------
__device__ __half g_xt[XT_ELEMS];            // style1-scaled x, NHWC padded, fp16
__device__ __half g_ht[XT_ELEMS];            // style2-scaled h, NHWC padded, fp16
__device__ __half g_wf[2][9][16][C_][16];    // weights fp16 [conv][tap][cin16][cout][cin&15]
__device__ float  g_wsq[2][C_][C_];
__device__ float  g_style[2][B_][C_];
__device__ float  g_demod[2][B_][C_];

// ---------------- PTX helpers ----------------
__device__ __forceinline__ uint32_t smem_u32(const void* p) {
    uint32_t a;
    asm("{ .reg .u64 t; cvta.to.shared.u64 t, %1; cvt.u32.u64 %0, t; }" : "=r"(a) : "l"(p));
    return a;
}
__device__ __forceinline__ void cp16(uint32_t s, const void* g) {
    asm volatile("cp.async.cg.shared.global [%0], [%1], 16;" :: "r"(s), "l"(g));
}
__device__ __forceinline__ void cp_commit() { asm volatile("cp.async.commit_group;" ::: "memory"); }
__device__ __forceinline__ void cp_wait0()  { asm volatile("cp.async.wait_group 0;" ::: "memory"); }
__device__ __forceinline__ void ldmx4(uint32_t* r, uint32_t a) {
    asm volatile("ldmatrix.sync.aligned.m8n8.x4.shared.b16 {%0,%1,%2,%3}, [%4];"
                 : "=r"(r[0]), "=r"(r[1]), "=r"(r[2]), "=r"(r[3]) : "r"(a));
}
__device__ __forceinline__ void mma16816(float* d, const uint32_t* a, const uint32_t* b) {
    asm volatile(
        "mma.sync.aligned.m16n8k16.row.col.f32.f16.f16.f32 "
        "{%0,%1,%2,%3}, {%4,%5,%6,%7}, {%8,%9}, {%0,%1,%2,%3};"
        : "+f"(d[0]), "+f"(d[1]), "+f"(d[2]), "+f"(d[3])
        : "r"(a[0]), "r"(a[1]), "r"(a[2]), "r"(a[3]), "r"(b[0]), "r"(b[1]));
}

// ================= prep1: wprep (blocks 0..511) + style (blocks 512..1535) ==========
#define PREP1_WBLOCKS 512     // 2*C*C / 256
#define PREP1_BLOCKS  1536
__global__ void prep1_kernel(const float* __restrict__ w1, const float* __restrict__ w2,
                             const float* __restrict__ w1v, const float* __restrict__ w2v,
                             const float* __restrict__ s1w, const float* __restrict__ s1b,
                             const float* __restrict__ s2w, const float* __restrict__ s2b) {
    if (blockIdx.x < PREP1_WBLOCKS) {
        int idx = blockIdx.x * 256 + threadIdx.x;     // 2*C*C
        int cv = idx >> 16, co = (idx >> 8) & 255, ci = idx & 255;
        const float* w = cv ? w2 : w1;
        float sq = 0.f;
        #pragma unroll
        for (int k = 0; k < 9; k++) {
            float v = w[(co * C_ + ci) * 9 + k];
            sq += v * v;
            g_wf[cv][k][ci >> 4][co][ci & 15] = __float2half(v);
        }
        g_wsq[cv][co][ci] = sq;
    } else {
        int gw = (blockIdx.x - PREP1_WBLOCKS) * 8 + (threadIdx.x >> 5);   // 2*B*C warps
        int lane = threadIdx.x & 31;
        int cv = gw >> 12, b = (gw >> 8) & 15, c = gw & 255;
        const float* wv = (cv ? w2v : w1v) + b * S_;
        const float* sr = (cv ? s2w : s1w) + c * S_;
        float sum = 0.f;
        #pragma unroll 4
        for (int s = lane; s < S_; s += 32) sum += wv[s] * sr[s];
        #pragma unroll
        for (int o = 16; o > 0; o >>= 1) sum += __shfl_down_sync(0xffffffffu, sum, o);
        if (lane == 0) g_style[cv][b][c] = sum * STYLE_SCALE + (cv ? s2b : s1b)[c];
    }
}

// ========= prep2: xprep (0..4095) + halo (4096..8255) + demod (8256..9279) ==========
#define PREP2_XBLOCKS 4096
#define PREP2_HBLOCKS 4160    // ceil(B*260*C / 256)
#define PREP2_BLOCKS  (PREP2_XBLOCKS + PREP2_HBLOCKS + 1024)
__global__ void prep2_kernel(const float* __restrict__ x) {
    __shared__ float t[64][65];
    __shared__ float st[64];
    const int tid = threadIdx.x;
    if (blockIdx.x < PREP2_XBLOCKS) {
        // ---- xprep: x (NCHW fp32) -> style1-scaled padded NHWC fp16 ----
        int blk = blockIdx.x;
        int c0 = (blk & 3) << 6, py = (blk >> 2) & 63, b = blk >> 8;
        if (tid < 64) st[tid] = g_style[0][b][c0 + tid];
        // float4 loads: 64 ci x 16 float4 per row = 1024 float4 -> 4 per thread
        {
            int ci0 = tid >> 4, f4 = tid & 15;
            #pragma unroll
            for (int i = 0; i < 4; i++) {
                int ci = ci0 + (i << 4);
                float4 v = *reinterpret_cast<const float4*>(
                    x + (((size_t)b * C_ + c0 + ci) << 12) + (py << 6) + (f4 << 2));
                t[ci][(f4 << 2) + 0] = v.x;
                t[ci][(f4 << 2) + 1] = v.y;
                t[ci][(f4 << 2) + 2] = v.z;
                t[ci][(f4 << 2) + 3] = v.w;
            }
        }
        __syncthreads();
        #pragma unroll 4
        for (int i = 0; i < 16; i++) {
            int px = (i << 2) + (tid >> 6), ci = tid & 63;
            float v = t[ci][px] * st[ci];
            size_t a = (((size_t)b * P_ + py + 1) * P_ + px + 1) * C_ + c0 + ci;
            g_xt[a] = __float2half(v);
        }
    } else if (blockIdx.x < PREP2_XBLOCKS + PREP2_HBLOCKS) {
        // ---- halo ring zeroing for both padded buffers ----
        int e = (blockIdx.x - PREP2_XBLOCKS) * 256 + tid;
        if (e >= B_ * 260 * C_) return;
        int ci = e & 255, tt = e >> 8, i = tt % 260, b = tt / 260;
        int py, px;
        if (i < 66)       { py = 0;       px = i; }
        else if (i < 132) { py = 65;      px = i - 66; }
        else if (i < 196) { py = i - 131; px = 0; }
        else              { py = i - 195; px = 65; }
        size_t a = (((size_t)b * P_ + py) * P_ + px) * C_ + ci;
        g_xt[a] = __float2half(0.f);
        g_ht[a] = __float2half(0.f);
    } else {
        // ---- demod ----
        int gw = (blockIdx.x - PREP2_XBLOCKS - PREP2_HBLOCKS) * 8 + (tid >> 5);
        int lane = tid & 31;
        int cv = gw >> 12, b = (gw >> 8) & 15, co = gw & 255;
        float sum = 0.f;
        #pragma unroll 4
        for (int ci = lane; ci < C_; ci += 32) {
            float s = g_style[cv][b][ci];
            sum += s * s * g_wsq[cv][co][ci];
        }
        #pragma unroll
        for (int o = 16; o > 0; o >>= 1) sum += __shfl_down_sync(0xffffffffu, sum, o);
        if (lane == 0) g_demod[cv][b][co] = rsqrtf(sum + EPS_);
    }
}

// ---------------- main conv: implicit GEMM, tap-reuse stages, occ 2 ----------------
// CTA: M=128 couts x N=128 px (2 image rows). Stage = cin16 chunk: B slab of
// 4 haloed rows x 66 px (8448B) + A 9 taps x 128 co (36864B). 16 stages,
// 2 slots, ONE __syncthreads per stage (wait0 -> sync -> load(s+1) -> compute(s)).
#define SLOT_B 8448
#define SLOT_A 36864
#define SLOT_BYTES (SLOT_B + SLOT_A)      // 45312
#define NSLOT 2
#define SMEM_CONV (NSLOT * SLOT_BYTES)    // 90624
#define NSTAGE 16

__device__ __forceinline__ uint32_t swz(int unit32, int half16) {
    return (uint32_t)((unit32 * 32 + half16) ^ (((unit32 >> 2) & 1) << 4));
}

__global__ __launch_bounds__(256, 2)
void conv_hmma_kernel(const __half* __restrict__ xt, int wsel,
                      const float* __restrict__ nw,
                      const float* __restrict__ noise, int mode,
                      __half* __restrict__ o_h, float* __restrict__ outp) {
    extern __shared__ __align__(128) char smem_raw[];
    const uint32_t sb = smem_u32(smem_raw);

    const int tid = threadIdx.x;
    const int wid = tid >> 5, lane = tid & 31;
    const int warp_m = wid & 3, warp_n = wid >> 2;
    const int n0 = blockIdx.x << 7;
    const int co0 = blockIdx.y << 7;
    const int b = blockIdx.z;
    const int r0 = blockIdx.x << 1;

    const int a_min  = (lane & 7) + ((lane >> 3) & 1) * 8;
    const int a_koff = (lane >> 4) << 4;
    const int b_nin  = ((lane >> 4) << 3) + (lane & 7);
    const int b_koff = ((lane >> 3) & 1) << 4;

    float acc[2][8][4];
    #pragma unroll
    for (int i = 0; i < 2; i++)
        #pragma unroll
        for (int j = 0; j < 8; j++)
            #pragma unroll
            for (int r = 0; r < 4; r++) acc[i][j][r] = 0.f;

    auto load_stage = [&](int s) {
        if (s < NSTAGE) {
            const uint32_t slot = sb + (s & 1) * SLOT_BYTES;
            const int cin0 = s << 4;
            #pragma unroll
            for (int i = tid; i < 528; i += 256) {
                int row = i / 132, rem = i - row * 132;
                int px = rem >> 1, u = rem & 1;
                cp16(slot + row * 2112 + swz(px, u << 4),
                     xt + ((((size_t)b * P_ + r0 + row) * P_ + px) << 8) + cin0 + (u << 3));
            }
            const __half* wbase = &g_wf[wsel][0][s][co0][0];
            #pragma unroll
            for (int i = tid; i < 2304; i += 256) {
                int tap = i >> 8, rem = i & 255;
                int co = rem >> 1, u = rem & 1;
                cp16(slot + SLOT_B + tap * 4096 + swz(co, u << 4),
                     wbase + (size_t)tap * (16 * C_ * 16) + co * 16 + u * 8);
            }
        }
        cp_commit();
    };

    load_stage(0);

    #pragma unroll 1
    for (int s = 0; s < NSTAGE; s++) {
        cp_wait0();             // stage s data complete (load(s+1) not yet issued)
        __syncthreads();        // visibility + slot (s+1)&1 free (compute(s-1) done)
        load_stage(s + 1);      // prefetch overlaps compute(s)
        const uint32_t slot = sb + (s & 1) * SLOT_BYTES;
        const uint32_t aslot = slot + SLOT_B;

        #pragma unroll
        for (int tap = 0; tap < 9; tap++) {
            const int dy = tap / 3, dx = tap - dy * 3;
            uint32_t a[2][4];
            #pragma unroll
            for (int f = 0; f < 2; f++) {
                int co_l = warp_m * 32 + f * 16 + a_min;
                ldmx4(a[f], aslot + tap * 4096 + swz(co_l, a_koff));
            }
            uint32_t bf[8][2];
            const uint32_t rowbase = slot + (warp_n + dy) * 2112;
            #pragma unroll
            for (int g = 0; g < 4; g++) {
                int ppx = g * 16 + b_nin + dx;
                uint32_t r[4];
                ldmx4(r, rowbase + swz(ppx, b_koff));
                bf[2 * g][0] = r[0]; bf[2 * g][1] = r[1];
                bf[2 * g + 1][0] = r[2]; bf[2 * g + 1][1] = r[3];
            }
            #pragma unroll
            for (int im = 0; im < 2; im++)
                #pragma unroll
                for (int in = 0; in < 8; in++)
                    mma16816(acc[im][in], a[im], bf[in]);
        }
    }
    __syncthreads();   // protect smem reuse in epilogue

    // ---------------- epilogue ----------------
    const int qm = lane >> 2;
    const int qn = (lane & 3) << 1;

    if (mode == 1) {
        #pragma unroll
        for (int im = 0; im < 2; im++) {
            #pragma unroll
            for (int rr = 0; rr < 2; rr++) {
                const int m = co0 + warp_m * 32 + im * 16 + qm + rr * 8;
                const float dm = g_demod[wsel][b][m];
                const float nwv = nw[m];
                float* ob = outp + (((size_t)b << 8) + m) * 4096;
                #pragma unroll
                for (int in = 0; in < 8; in++) {
                    const int n = n0 + warp_n * 64 + in * 8 + qn;
                    float v0 = acc[im][in][rr * 2 + 0] * dm + nwv * noise[((size_t)b << 12) + n];
                    float v1 = acc[im][in][rr * 2 + 1] * dm + nwv * noise[((size_t)b << 12) + n + 1];
                    v0 = v0 > 0.f ? v0 : 0.2f * v0;
                    v1 = v1 > 0.f ? v1 : 0.2f * v1;
                    *reinterpret_cast<float2*>(ob + n) = make_float2(v0, v1);
                }
            }
        }
    } else {
        __half* hs = reinterpret_cast<__half*>(smem_raw);   // [128 n][stride 136]
        #pragma unroll
        for (int im = 0; im < 2; im++) {
            #pragma unroll
            for (int rr = 0; rr < 2; rr++) {
                const int ml = warp_m * 32 + im * 16 + qm + rr * 8;
                const int m = co0 + ml;
                const float dm = g_demod[wsel][b][m];
                const float nwv = nw[m];
                const float sty = g_style[1][b][m];
                #pragma unroll
                for (int in = 0; in < 8; in++) {
                    const int nl = warp_n * 64 + in * 8 + qn;
                    const int n = n0 + nl;
                    float v0 = acc[im][in][rr * 2 + 0] * dm + nwv * noise[((size_t)b << 12) + n];
                    float v1 = acc[im][in][rr * 2 + 1] * dm + nwv * noise[((size_t)b << 12) + n + 1];
                    v0 = (v0 > 0.f ? v0 : 0.2f * v0) * sty;
                    v1 = (v1 > 0.f ? v1 : 0.2f * v1) * sty;
                    hs[nl * 136 + ml] = __float2half(v0);
                    hs[(nl + 1) * 136 + ml] = __float2half(v1);
                }
            }
        }
        __syncthreads();
        const int nl = tid >> 1, half = tid & 1;
        const int pix = n0 + nl;
        const int py = (pix >> 6) + 1, px = (pix & 63) + 1;
        const uint4* src = reinterpret_cast<const uint4*>(hs + nl * 136 + half * 64);
        uint4* dst = reinterpret_cast<uint4*>(
            o_h + ((((size_t)b * P_ + py) * P_ + px) << 8) + co0 + half * 64);
        #pragma unroll
        for (int i = 0; i < 8; i++) dst[i] = src[i];
    }
}

// ---------------- launcher ----------------
extern "C" void kernel_launch(void* const* d_in, const int* in_sizes, int n_in,
                              void* d_out, int out_size) {
    const float* x       = (const float*)d_in[0];
    const float* w1      = (const float*)d_in[1];
    const float* w2      = (const float*)d_in[2];
    const float* noise1  = (const float*)d_in[3];
    const float* noise2  = (const float*)d_in[4];
    const float* s1_w    = (const float*)d_in[5];
    const float* s1_b    = (const float*)d_in[6];
    const float* conv1_w = (const float*)d_in[7];
    const float* nw1     = (const float*)d_in[8];
    const float* s2_w    = (const float*)d_in[9];
    const float* s2_b    = (const float*)d_in[10];
    const float* conv2_w = (const float*)d_in[11];
    const float* nw2     = (const float*)d_in[12];
    float* out = (float*)d_out;

    __half *p_xt, *p_ht;
    cudaGetSymbolAddress((void**)&p_xt, g_xt);
    cudaGetSymbolAddress((void**)&p_ht, g_ht);

    cudaFuncSetAttribute(conv_hmma_kernel,
                         cudaFuncAttributeMaxDynamicSharedMemorySize, SMEM_CONV);

    prep1_kernel<<<PREP1_BLOCKS, 256>>>(conv1_w, conv2_w, w1, w2,
                                        s1_w, s1_b, s2_w, s2_b);
    prep2_kernel<<<PREP2_BLOCKS, 256>>>(x);

    dim3 grid(32, 2, 16);
    conv_hmma_kernel<<<grid, 256, SMEM_CONV>>>(p_xt, 0, nw1, noise1, 0, p_ht, nullptr);
    conv_hmma_kernel<<<grid, 256, SMEM_CONV>>>(p_ht, 1, nw2, noise2, 1, nullptr, out);
}